// round 1
// baseline (speedup 1.0000x reference)
#include <cuda_runtime.h>
#include <math.h>
#include <float.h>

#define BB    2
#define SS    2048
#define HID   2048
#define NH    16
#define NG    4
#define DK    128
#define NHPG  4
#define BSTOK (BB*SS)

// Scratch (allocation-free rule: __device__ globals)
static __device__ float g_q  [BSTOK * HID];          // [b*s, 16*128]  Q after proj (+rope in place)
static __device__ float g_kv [BSTOK * 2 * NG * DK];  // [b*s, 1024]    K|V packed  (+rope on K in place)
static __device__ float g_ctx[BSTOK * HID];          // [b*s, 16*128]  attention output

// ---------------------------------------------------------------------------
// SGEMM: C[M,N] = A[M,K] @ B[K,N], row-major, 128x128 block tile, 8x8/thread
// M,N,K multiples of 128/8 (all true here).
// ---------------------------------------------------------------------------
__global__ __launch_bounds__(256) void sgemm128(const float* __restrict__ A,
                                                const float* __restrict__ Bm,
                                                float* __restrict__ C,
                                                int M, int N, int K)
{
    __shared__ float As[8][128];
    __shared__ float Bs[8][128];

    const int tid = threadIdx.x;
    const int tx  = tid & 15;
    const int ty  = tid >> 4;
    const int bm  = blockIdx.y * 128;
    const int bn  = blockIdx.x * 128;

    float acc[8][8];
#pragma unroll
    for (int i = 0; i < 8; i++)
#pragma unroll
        for (int j = 0; j < 8; j++) acc[i][j] = 0.0f;

    const int aRow = bm + (tid >> 1);
    const int aCol = (tid & 1) * 4;
    const int bRow = tid >> 5;
    const int bCol = bn + (tid & 31) * 4;
    const float* Ap = A  + (size_t)aRow * K + aCol;
    const float* Bp = Bm + (size_t)bRow * N + bCol;

    for (int k0 = 0; k0 < K; k0 += 8) {
        float4 av = *(const float4*)(Ap + k0);
        float4 bv = *(const float4*)(Bp + (size_t)k0 * N);
        As[aCol + 0][tid >> 1] = av.x;
        As[aCol + 1][tid >> 1] = av.y;
        As[aCol + 2][tid >> 1] = av.z;
        As[aCol + 3][tid >> 1] = av.w;
        *(float4*)&Bs[bRow][(tid & 31) * 4] = bv;
        __syncthreads();

#pragma unroll
        for (int kk = 0; kk < 8; kk++) {
            float4 a0 = *(float4*)&As[kk][ty * 8];
            float4 a1 = *(float4*)&As[kk][ty * 8 + 4];
            float4 b0 = *(float4*)&Bs[kk][tx * 8];
            float4 b1 = *(float4*)&Bs[kk][tx * 8 + 4];
            float ra[8] = {a0.x, a0.y, a0.z, a0.w, a1.x, a1.y, a1.z, a1.w};
            float rb[8] = {b0.x, b0.y, b0.z, b0.w, b1.x, b1.y, b1.z, b1.w};
#pragma unroll
            for (int i = 0; i < 8; i++)
#pragma unroll
                for (int j = 0; j < 8; j++) acc[i][j] += ra[i] * rb[j];
        }
        __syncthreads();
    }

#pragma unroll
    for (int i = 0; i < 8; i++) {
        float* cp = C + (size_t)(bm + ty * 8 + i) * N + bn + tx * 8;
        *(float4*)cp       = make_float4(acc[i][0], acc[i][1], acc[i][2], acc[i][3]);
        *(float4*)(cp + 4) = make_float4(acc[i][4], acc[i][5], acc[i][6], acc[i][7]);
    }
}

// ---------------------------------------------------------------------------
// RoPE (in place). Phase computed in double so our phase error is below the
// reference's own fp32 rounding (~1e-4 rad worst case).
// ---------------------------------------------------------------------------
__global__ void rope_q_kernel()
{
    int idx = blockIdx.x * blockDim.x + threadIdx.x;   // BSTOK*NH*64
    int j   = idx & 63;
    int h   = (idx >> 6) & (NH - 1);
    int tok = idx >> 10;
    if (tok >= BSTOK) return;
    int t = tok & (SS - 1);
    float* p = g_q + (size_t)tok * HID + h * DK + j;
    float x1 = p[0], x2 = p[64];
    double invf = exp(-9.210340371976184 * (double)j / 64.0);  // ln(10000)
    float  f    = (float)((double)t * invf);
    float c, s;
    sincosf(f, &s, &c);
    p[0]  = x1 * c - x2 * s;
    p[64] = x2 * c + x1 * s;
}

__global__ void rope_k_kernel()
{
    int idx = blockIdx.x * blockDim.x + threadIdx.x;   // BSTOK*NG*64
    int j   = idx & 63;
    int g   = (idx >> 6) & (NG - 1);
    int tok = idx >> 8;
    if (tok >= BSTOK) return;
    int t = tok & (SS - 1);
    float* p = g_kv + (size_t)tok * (2 * NG * DK) + g * DK + j;   // K half (sel=0)
    float x1 = p[0], x2 = p[64];
    double invf = exp(-9.210340371976184 * (double)j / 64.0);
    float  f    = (float)((double)t * invf);
    float c, s;
    sincosf(f, &s, &c);
    p[0]  = x1 * c - x2 * s;
    p[64] = x2 * c + x1 * s;
}

// ---------------------------------------------------------------------------
// Flash attention, causal, fp32. Grid: (S/64, NH, B). Block: 256 threads.
// Tiles: 64 queries x 64 keys x d=128. Online softmax, per-thread 4x4 score
// microtile and 4x8 output microtile; 16-lane shuffle row reductions.
// ---------------------------------------------------------------------------
#define QROWS 64
#define KCOLS 64
#define LDQ   132      // 128 + 4 pad (float4-aligned, breaks bank conflicts)
#define LDP   68

__global__ __launch_bounds__(256) void flash_kernel()
{
    extern __shared__ float sm[];
    float* Qs = sm;                        // 64*132
    float* Ks = Qs + QROWS * LDQ;          // 64*132
    float* Vs = Ks + KCOLS * LDQ;          // 64*132
    float* Ps = Vs + KCOLS * LDQ;          // 64*68

    const int tid = threadIdx.x;
    const int tx  = tid & 15;
    const int ty  = tid >> 4;
    const int qt  = blockIdx.x;
    const int h   = blockIdx.y;
    const int b   = blockIdx.z;
    const int g   = h / NHPG;
    const int q0  = qt * QROWS;
    const float scale = 0.08838834764831845f;   // 1/sqrt(128)

    // load Q tile (pre-scaled)
#pragma unroll
    for (int i = 0; i < 8; i++) {
        int idx = tid + i * 256;           // float4 units; 64 rows * 32 f4/row
        int r = idx >> 5, c4 = (idx & 31) * 4;
        float4 v = *(const float4*)&g_q[(size_t)(b * SS + q0 + r) * HID + h * DK + c4];
        v.x *= scale; v.y *= scale; v.z *= scale; v.w *= scale;
        *(float4*)&Qs[r * LDQ + c4] = v;
    }

    float m_[4], l_[4], acc[4][8];
#pragma unroll
    for (int i = 0; i < 4; i++) {
        m_[i] = -3.0e38f; l_[i] = 0.0f;
#pragma unroll
        for (int j = 0; j < 8; j++) acc[i][j] = 0.0f;
    }

    for (int kt = 0; kt <= qt; kt++) {
        __syncthreads();                   // protect smem reuse (also covers Q load)
        const int kbase = kt * KCOLS;
#pragma unroll
        for (int i = 0; i < 8; i++) {
            int idx = tid + i * 256;
            int r = idx >> 5, c4 = (idx & 31) * 4;
            const float* kvp = &g_kv[(size_t)(b * SS + kbase + r) * (2 * NG * DK) + g * DK + c4];
            *(float4*)&Ks[r * LDQ + c4] = *(const float4*)kvp;
            *(float4*)&Vs[r * LDQ + c4] = *(const float4*)(kvp + NG * DK);
        }
        __syncthreads();

        // S = Q @ K^T  (4x4 per thread)
        float s[4][4];
#pragma unroll
        for (int i = 0; i < 4; i++)
#pragma unroll
            for (int j = 0; j < 4; j++) s[i][j] = 0.0f;

        for (int d = 0; d < DK; d += 4) {
            float4 qv[4], kv[4];
#pragma unroll
            for (int i = 0; i < 4; i++) qv[i] = *(float4*)&Qs[(ty * 4 + i) * LDQ + d];
#pragma unroll
            for (int j = 0; j < 4; j++) kv[j] = *(float4*)&Ks[(tx * 4 + j) * LDQ + d];
#pragma unroll
            for (int i = 0; i < 4; i++)
#pragma unroll
                for (int j = 0; j < 4; j++)
                    s[i][j] += qv[i].x * kv[j].x + qv[i].y * kv[j].y
                             + qv[i].z * kv[j].z + qv[i].w * kv[j].w;
        }

        const bool diag = (kt == qt);
#pragma unroll
        for (int i = 0; i < 4; i++) {
            int qg = q0 + ty * 4 + i;
            float sv[4], mx = -3.0e38f;
#pragma unroll
            for (int j = 0; j < 4; j++) {
                float v = s[i][j];
                if (diag && (kbase + tx * 4 + j) > qg) v = -3.0e38f;
                sv[j] = v;
                mx = fmaxf(mx, v);
            }
#pragma unroll
            for (int o = 8; o >= 1; o >>= 1)
                mx = fmaxf(mx, __shfl_xor_sync(0xffffffffu, mx, o));
            float mnew = fmaxf(m_[i], mx);
            float corr = __expf(m_[i] - mnew);
            float p0 = __expf(sv[0] - mnew);
            float p1 = __expf(sv[1] - mnew);
            float p2 = __expf(sv[2] - mnew);
            float p3 = __expf(sv[3] - mnew);
            *(float4*)&Ps[(ty * 4 + i) * LDP + tx * 4] = make_float4(p0, p1, p2, p3);
            float rs = p0 + p1 + p2 + p3;
#pragma unroll
            for (int o = 8; o >= 1; o >>= 1)
                rs += __shfl_xor_sync(0xffffffffu, rs, o);
            l_[i] = l_[i] * corr + rs;
            m_[i] = mnew;
#pragma unroll
            for (int j = 0; j < 8; j++) acc[i][j] *= corr;
        }
        __syncthreads();

        // O += P @ V  (cols tx*4 .. +3 and 64+tx*4 .. +3)
        for (int k = 0; k < KCOLS; k++) {
            float4 v0 = *(float4*)&Vs[k * LDQ + tx * 4];
            float4 v1 = *(float4*)&Vs[k * LDQ + 64 + tx * 4];
#pragma unroll
            for (int i = 0; i < 4; i++) {
                float p = Ps[(ty * 4 + i) * LDP + k];
                acc[i][0] += p * v0.x; acc[i][1] += p * v0.y;
                acc[i][2] += p * v0.z; acc[i][3] += p * v0.w;
                acc[i][4] += p * v1.x; acc[i][5] += p * v1.y;
                acc[i][6] += p * v1.z; acc[i][7] += p * v1.w;
            }
        }
    }

#pragma unroll
    for (int i = 0; i < 4; i++) {
        float inv = 1.0f / l_[i];
        int r = q0 + ty * 4 + i;
        float* cp = &g_ctx[(size_t)(b * SS + r) * HID + h * DK];
        *(float4*)(cp + tx * 4)      = make_float4(acc[i][0] * inv, acc[i][1] * inv,
                                                   acc[i][2] * inv, acc[i][3] * inv);
        *(float4*)(cp + 64 + tx * 4) = make_float4(acc[i][4] * inv, acc[i][5] * inv,
                                                   acc[i][6] * inv, acc[i][7] * inv);
    }
}

// ---------------------------------------------------------------------------
extern "C" void kernel_launch(void* const* d_in, const int* in_sizes, int n_in,
                              void* d_out, int out_size)
{
    const float* x       = (const float*)d_in[0];
    const float* w_q     = (const float*)d_in[1];
    const float* w_kv    = (const float*)d_in[2];
    const float* w_dense = (const float*)d_in[3];
    float* out = (float*)d_out;

    float *qp, *kvp, *ctxp;
    cudaGetSymbolAddress((void**)&qp,   g_q);
    cudaGetSymbolAddress((void**)&kvp,  g_kv);
    cudaGetSymbolAddress((void**)&ctxp, g_ctx);

    // projections
    sgemm128<<<dim3(HID / 128, BSTOK / 128), 256>>>(x, w_q, qp, BSTOK, HID, HID);
    sgemm128<<<dim3((2 * NG * DK) / 128, BSTOK / 128), 256>>>(x, w_kv, kvp, BSTOK, 2 * NG * DK, HID);

    // rope
    rope_q_kernel<<<(BSTOK * NH * 64) / 256, 256>>>();
    rope_k_kernel<<<(BSTOK * NG * 64) / 256, 256>>>();

    // attention
    size_t smem = (size_t)(3 * QROWS * LDQ + QROWS * LDP) * sizeof(float);
    cudaFuncSetAttribute(flash_kernel, cudaFuncAttributeMaxDynamicSharedMemorySize, (int)smem);
    flash_kernel<<<dim3(SS / QROWS, NH, BB), 256, smem>>>();

    // output projection
    sgemm128<<<dim3(HID / 128, BSTOK / 128), 256>>>(ctxp, w_dense, out, BSTOK, HID, HID);
}

// round 3
// speedup vs baseline: 1.5047x; 1.5047x over previous
#include <cuda_runtime.h>
#include <cuda_bf16.h>
#include <cstdint>
#include <math.h>

#define BB    2
#define SS    2048
#define HID   2048
#define NH    16
#define NG    4
#define DK    128
#define NHPG  4
#define BSTOK (BB*SS)
#define KDIM  2048

// ---------------------------------------------------------------------------
// Scratch (__device__ globals; allocation-free rule)
// ---------------------------------------------------------------------------
static __device__ float g_q  [BSTOK * HID];
static __device__ float g_kv [BSTOK * 2 * NG * DK];
static __device__ float g_ctx[BSTOK * HID];

static __device__ __nv_bfloat16 g_xh [BSTOK * KDIM];
static __device__ __nv_bfloat16 g_xl [BSTOK * KDIM];
static __device__ __nv_bfloat16 g_wqh [HID * KDIM];
static __device__ __nv_bfloat16 g_wql [HID * KDIM];
static __device__ __nv_bfloat16 g_wkvh[(2*NG*DK) * KDIM];
static __device__ __nv_bfloat16 g_wkvl[(2*NG*DK) * KDIM];
static __device__ __nv_bfloat16 g_wdh [HID * KDIM];
static __device__ __nv_bfloat16 g_wdl [HID * KDIM];
static __device__ __nv_bfloat16 g_ch [BSTOK * KDIM];
static __device__ __nv_bfloat16 g_cl [BSTOK * KDIM];

// ---------------------------------------------------------------------------
// cp.async helper (sm_80+, base-target safe)
// ---------------------------------------------------------------------------
__device__ __forceinline__ void cp_async16(uint32_t s, const void* g) {
    asm volatile("cp.async.cg.shared.global [%0], [%1], 16;\n" :: "r"(s), "l"(g) : "memory");
}
__device__ __forceinline__ void cp_commit() {
    asm volatile("cp.async.commit_group;\n" ::: "memory");
}

// mma.sync m16n8k16 bf16 -> f32 (base-target safe, HMMA on sm_103)
__device__ __forceinline__ void mma16816(float* c, const uint32_t* a, const uint32_t* b)
{
    asm volatile(
        "mma.sync.aligned.m16n8k16.row.col.f32.bf16.bf16.f32 "
        "{%0,%1,%2,%3}, {%4,%5,%6,%7}, {%8,%9}, {%0,%1,%2,%3};"
        : "+f"(c[0]), "+f"(c[1]), "+f"(c[2]), "+f"(c[3])
        : "r"(a[0]), "r"(a[1]), "r"(a[2]), "r"(a[3]), "r"(b[0]), "r"(b[1]));
}

// ---------------------------------------------------------------------------
// Prep: fp32 -> (bf16 hi, bf16 lo) elementwise split
// ---------------------------------------------------------------------------
__global__ void prep_split(const float* __restrict__ src,
                           __nv_bfloat16* __restrict__ h,
                           __nv_bfloat16* __restrict__ l, int n4)
{
    int i = blockIdx.x * blockDim.x + threadIdx.x;
    if (i >= n4) return;
    float4 v = ((const float4*)src)[i];
    float vv[4] = {v.x, v.y, v.z, v.w};
    __nv_bfloat16 hh[4], ll[4];
#pragma unroll
    for (int j = 0; j < 4; j++) {
        hh[j] = __float2bfloat16_rn(vv[j]);
        ll[j] = __float2bfloat16_rn(vv[j] - __bfloat162float(hh[j]));
    }
    ((uint2*)h)[i] = *(uint2*)hh;
    ((uint2*)l)[i] = *(uint2*)ll;
}

// ---------------------------------------------------------------------------
// Prep: transpose W[K, N] fp32 -> WT hi/lo [N, K] bf16
// ---------------------------------------------------------------------------
__global__ void transpose_split(const float* __restrict__ W,
                                __nv_bfloat16* __restrict__ Th,
                                __nv_bfloat16* __restrict__ Tl, int Ncols)
{
    __shared__ float tile[32][33];
    int n = blockIdx.x * 32 + threadIdx.x;
    int k0 = blockIdx.y * 32;
#pragma unroll
    for (int r = 0; r < 4; r++) {
        int k = k0 + threadIdx.y + r * 8;
        tile[threadIdx.y + r * 8][threadIdx.x] = W[(size_t)k * Ncols + n];
    }
    __syncthreads();
#pragma unroll
    for (int r = 0; r < 4; r++) {
        int nn = blockIdx.x * 32 + threadIdx.y + r * 8;
        int kk = k0 + threadIdx.x;
        float v = tile[threadIdx.x][threadIdx.y + r * 8];
        __nv_bfloat16 hh = __float2bfloat16_rn(v);
        Th[(size_t)nn * KDIM + kk] = hh;
        Tl[(size_t)nn * KDIM + kk] = __float2bfloat16_rn(v - __bfloat162float(hh));
    }
}

// ---------------------------------------------------------------------------
// mma.sync GEMM: C[M,N] = A[M,K] @ B[K,N] via bf16x3 split, fp32 accum.
// A as Ah/Al [M,K] bf16 row-major; B transposed Bh/Bl [N,K] bf16 row-major
// (== .col operand layout for mma). Tile 128x128, K-chunk 64, double-buffered
// cp.async. 256 threads = 8 warps in 2(M) x 4(N) grid; 64x32 per warp.
// Smem rows padded to 144 B (word stride 36 = 4 mod 32 -> conflict-free).
// ---------------------------------------------------------------------------
#define LDB    144                 // bytes per smem row (64 bf16 + 8 pad)
#define TILEB  (128 * LDB)         // 18432 B per tile
#define STAGEB (4 * TILEB)         // Ah | Al | Bh | Bl
#define GEMM_SMEM (2 * STAGEB)     // 147456 B

__device__ __forceinline__ void load_chunk_mma(
    const __nv_bfloat16* __restrict__ Ah, const __nv_bfloat16* __restrict__ Al,
    const __nv_bfloat16* __restrict__ Bh, const __nv_bfloat16* __restrict__ Bl,
    int m0, int n0, int k0, uint32_t stage, int tid)
{
#pragma unroll
    for (int i = 0; i < 16; i++) {
        int lin = i * 256 + tid;            // 0..4095
        int t   = lin >> 10;                // 0:Ah 1:Al 2:Bh 3:Bl
        int rem = lin & 1023;
        int row = rem >> 3;
        int c   = rem & 7;                  // 16B chunk within 128B row
        const __nv_bfloat16* base = (t == 0) ? Ah : (t == 1) ? Al : (t == 2) ? Bh : Bl;
        int grow = ((t < 2) ? m0 : n0) + row;
        const __nv_bfloat16* gp = base + (size_t)grow * KDIM + k0 + c * 8;
        cp_async16(stage + t * TILEB + row * LDB + c * 16, gp);
    }
    cp_commit();
}

__global__ __launch_bounds__(256) void gemm_mma(
    const __nv_bfloat16* __restrict__ Ah, const __nv_bfloat16* __restrict__ Al,
    const __nv_bfloat16* __restrict__ Bh, const __nv_bfloat16* __restrict__ Bl,
    float* __restrict__ C, int N)
{
    extern __shared__ char smc[];
    uint32_t sb = (uint32_t)__cvta_generic_to_shared(smc);
    const int tid  = threadIdx.x;
    const int wid  = tid >> 5;
    const int lane = tid & 31;
    const int wm = wid >> 2;            // 0..1
    const int wn = wid & 3;             // 0..3
    const int m0 = blockIdx.y * 128;
    const int n0 = blockIdx.x * 128;
    const int r  = lane >> 2;           // 0..7
    const int kq = (lane & 3) * 2;      // 0,2,4,6

    float acc[4][4][4];
#pragma unroll
    for (int mt = 0; mt < 4; mt++)
#pragma unroll
        for (int nt = 0; nt < 4; nt++)
#pragma unroll
            for (int j = 0; j < 4; j++) acc[mt][nt][j] = 0.0f;

    const int NC = KDIM / 64;           // 32
    load_chunk_mma(Ah, Al, Bh, Bl, m0, n0, 0, sb, tid);

    for (int c = 0; c < NC; c++) {
        const uint32_t stg = sb + (uint32_t)(c & 1) * STAGEB;
        if (c + 1 < NC) {
            load_chunk_mma(Ah, Al, Bh, Bl, m0, n0, (c + 1) * 64,
                           sb + (uint32_t)((c + 1) & 1) * STAGEB, tid);
            asm volatile("cp.async.wait_group 1;\n" ::: "memory");
        } else {
            asm volatile("cp.async.wait_group 0;\n" ::: "memory");
        }
        __syncthreads();

        const char* sA  = smc + (stg - sb);
        const char* sAl = sA + TILEB;
        const char* sBh = sA + 2 * TILEB;
        const char* sBl = sA + 3 * TILEB;

#pragma unroll
        for (int ks = 0; ks < 4; ks++) {
            const int k0 = ks * 16;
            uint32_t ah[4][4], al[4][4], bh[4][2], bl[4][2];
#pragma unroll
            for (int mt = 0; mt < 4; mt++) {
                int row = wm * 64 + mt * 16 + r;
                ah[mt][0] = *(const uint32_t*)(sA  + (size_t)row       * LDB + (k0 + kq) * 2);
                ah[mt][1] = *(const uint32_t*)(sA  + (size_t)(row + 8) * LDB + (k0 + kq) * 2);
                ah[mt][2] = *(const uint32_t*)(sA  + (size_t)row       * LDB + (k0 + kq + 8) * 2);
                ah[mt][3] = *(const uint32_t*)(sA  + (size_t)(row + 8) * LDB + (k0 + kq + 8) * 2);
                al[mt][0] = *(const uint32_t*)(sAl + (size_t)row       * LDB + (k0 + kq) * 2);
                al[mt][1] = *(const uint32_t*)(sAl + (size_t)(row + 8) * LDB + (k0 + kq) * 2);
                al[mt][2] = *(const uint32_t*)(sAl + (size_t)row       * LDB + (k0 + kq + 8) * 2);
                al[mt][3] = *(const uint32_t*)(sAl + (size_t)(row + 8) * LDB + (k0 + kq + 8) * 2);
            }
#pragma unroll
            for (int nt = 0; nt < 4; nt++) {
                int nr = wn * 32 + nt * 8 + r;
                bh[nt][0] = *(const uint32_t*)(sBh + (size_t)nr * LDB + (k0 + kq) * 2);
                bh[nt][1] = *(const uint32_t*)(sBh + (size_t)nr * LDB + (k0 + kq + 8) * 2);
                bl[nt][0] = *(const uint32_t*)(sBl + (size_t)nr * LDB + (k0 + kq) * 2);
                bl[nt][1] = *(const uint32_t*)(sBl + (size_t)nr * LDB + (k0 + kq + 8) * 2);
            }
#pragma unroll
            for (int mt = 0; mt < 4; mt++)
#pragma unroll
                for (int nt = 0; nt < 4; nt++) {
                    mma16816(acc[mt][nt], ah[mt], bh[nt]);
                    mma16816(acc[mt][nt], ah[mt], bl[nt]);
                    mma16816(acc[mt][nt], al[mt], bh[nt]);
                }
        }
        __syncthreads();
    }

    // epilogue
#pragma unroll
    for (int mt = 0; mt < 4; mt++) {
#pragma unroll
        for (int nt = 0; nt < 4; nt++) {
            int row = m0 + wm * 64 + mt * 16 + r;
            int col = n0 + wn * 32 + nt * 8 + kq;
            *(float2*)&C[(size_t)row * N + col]       = make_float2(acc[mt][nt][0], acc[mt][nt][1]);
            *(float2*)&C[(size_t)(row + 8) * N + col] = make_float2(acc[mt][nt][2], acc[mt][nt][3]);
        }
    }
}

// ---------------------------------------------------------------------------
// RoPE (in place), float path
// ---------------------------------------------------------------------------
__global__ void rope_q_kernel()
{
    int idx = blockIdx.x * blockDim.x + threadIdx.x;
    int j   = idx & 63;
    int h   = (idx >> 6) & (NH - 1);
    int tok = idx >> 10;
    if (tok >= BSTOK) return;
    int t = tok & (SS - 1);
    float* p = g_q + (size_t)tok * HID + h * DK + j;
    float x1 = p[0], x2 = p[64];
    float invf = exp2f(-0.20762050593045935f * (float)j);
    float f = (float)t * invf;
    float c, s;
    sincosf(f, &s, &c);
    p[0]  = x1 * c - x2 * s;
    p[64] = x2 * c + x1 * s;
}

__global__ void rope_k_kernel()
{
    int idx = blockIdx.x * blockDim.x + threadIdx.x;
    int j   = idx & 63;
    int g   = (idx >> 6) & (NG - 1);
    int tok = idx >> 8;
    if (tok >= BSTOK) return;
    int t = tok & (SS - 1);
    float* p = g_kv + (size_t)tok * (2 * NG * DK) + g * DK + j;
    float x1 = p[0], x2 = p[64];
    float invf = exp2f(-0.20762050593045935f * (float)j);
    float f = (float)t * invf;
    float c, s;
    sincosf(f, &s, &c);
    p[0]  = x1 * c - x2 * s;
    p[64] = x2 * c + x1 * s;
}

// ---------------------------------------------------------------------------
// Flash attention, causal, fp32 (unchanged)
// ---------------------------------------------------------------------------
#define QROWS 64
#define KCOLS 64
#define LDQ   132
#define LDP   68

__global__ __launch_bounds__(256) void flash_kernel()
{
    extern __shared__ float sm[];
    float* Qs = sm;
    float* Ks = Qs + QROWS * LDQ;
    float* Vs = Ks + KCOLS * LDQ;
    float* Ps = Vs + KCOLS * LDQ;

    const int tid = threadIdx.x;
    const int tx  = tid & 15;
    const int ty  = tid >> 4;
    const int qt  = blockIdx.x;
    const int h   = blockIdx.y;
    const int b   = blockIdx.z;
    const int g   = h / NHPG;
    const int q0  = qt * QROWS;
    const float scale = 0.08838834764831845f;

#pragma unroll
    for (int i = 0; i < 8; i++) {
        int idx = tid + i * 256;
        int r = idx >> 5, c4 = (idx & 31) * 4;
        float4 v = *(const float4*)&g_q[(size_t)(b * SS + q0 + r) * HID + h * DK + c4];
        v.x *= scale; v.y *= scale; v.z *= scale; v.w *= scale;
        *(float4*)&Qs[r * LDQ + c4] = v;
    }

    float m_[4], l_[4], acc[4][8];
#pragma unroll
    for (int i = 0; i < 4; i++) {
        m_[i] = -3.0e38f; l_[i] = 0.0f;
#pragma unroll
        for (int j = 0; j < 8; j++) acc[i][j] = 0.0f;
    }

    for (int kt = 0; kt <= qt; kt++) {
        __syncthreads();
        const int kbase = kt * KCOLS;
#pragma unroll
        for (int i = 0; i < 8; i++) {
            int idx = tid + i * 256;
            int r = idx >> 5, c4 = (idx & 31) * 4;
            const float* kvp = &g_kv[(size_t)(b * SS + kbase + r) * (2 * NG * DK) + g * DK + c4];
            *(float4*)&Ks[r * LDQ + c4] = *(const float4*)kvp;
            *(float4*)&Vs[r * LDQ + c4] = *(const float4*)(kvp + NG * DK);
        }
        __syncthreads();

        float s[4][4];
#pragma unroll
        for (int i = 0; i < 4; i++)
#pragma unroll
            for (int j = 0; j < 4; j++) s[i][j] = 0.0f;

        for (int d = 0; d < DK; d += 4) {
            float4 qv[4], kv[4];
#pragma unroll
            for (int i = 0; i < 4; i++) qv[i] = *(float4*)&Qs[(ty * 4 + i) * LDQ + d];
#pragma unroll
            for (int j = 0; j < 4; j++) kv[j] = *(float4*)&Ks[(tx * 4 + j) * LDQ + d];
#pragma unroll
            for (int i = 0; i < 4; i++)
#pragma unroll
                for (int j = 0; j < 4; j++)
                    s[i][j] += qv[i].x * kv[j].x + qv[i].y * kv[j].y
                             + qv[i].z * kv[j].z + qv[i].w * kv[j].w;
        }

        const bool diag = (kt == qt);
#pragma unroll
        for (int i = 0; i < 4; i++) {
            int qg = q0 + ty * 4 + i;
            float sv[4], mx = -3.0e38f;
#pragma unroll
            for (int j = 0; j < 4; j++) {
                float v = s[i][j];
                if (diag && (kbase + tx * 4 + j) > qg) v = -3.0e38f;
                sv[j] = v;
                mx = fmaxf(mx, v);
            }
#pragma unroll
            for (int o = 8; o >= 1; o >>= 1)
                mx = fmaxf(mx, __shfl_xor_sync(0xffffffffu, mx, o));
            float mnew = fmaxf(m_[i], mx);
            float corr = __expf(m_[i] - mnew);
            float p0 = __expf(sv[0] - mnew);
            float p1 = __expf(sv[1] - mnew);
            float p2 = __expf(sv[2] - mnew);
            float p3 = __expf(sv[3] - mnew);
            *(float4*)&Ps[(ty * 4 + i) * LDP + tx * 4] = make_float4(p0, p1, p2, p3);
            float rs = p0 + p1 + p2 + p3;
#pragma unroll
            for (int o = 8; o >= 1; o >>= 1)
                rs += __shfl_xor_sync(0xffffffffu, rs, o);
            l_[i] = l_[i] * corr + rs;
            m_[i] = mnew;
#pragma unroll
            for (int j = 0; j < 8; j++) acc[i][j] *= corr;
        }
        __syncthreads();

        for (int k = 0; k < KCOLS; k++) {
            float4 v0 = *(float4*)&Vs[k * LDQ + tx * 4];
            float4 v1 = *(float4*)&Vs[k * LDQ + 64 + tx * 4];
#pragma unroll
            for (int i = 0; i < 4; i++) {
                float p = Ps[(ty * 4 + i) * LDP + k];
                acc[i][0] += p * v0.x; acc[i][1] += p * v0.y;
                acc[i][2] += p * v0.z; acc[i][3] += p * v0.w;
                acc[i][4] += p * v1.x; acc[i][5] += p * v1.y;
                acc[i][6] += p * v1.z; acc[i][7] += p * v1.w;
            }
        }
    }

#pragma unroll
    for (int i = 0; i < 4; i++) {
        float inv = 1.0f / l_[i];
        int r = q0 + ty * 4 + i;
        float* cp = &g_ctx[(size_t)(b * SS + r) * HID + h * DK];
        *(float4*)(cp + tx * 4)      = make_float4(acc[i][0] * inv, acc[i][1] * inv,
                                                   acc[i][2] * inv, acc[i][3] * inv);
        *(float4*)(cp + 64 + tx * 4) = make_float4(acc[i][4] * inv, acc[i][5] * inv,
                                                   acc[i][6] * inv, acc[i][7] * inv);
    }
}

// ---------------------------------------------------------------------------
extern "C" void kernel_launch(void* const* d_in, const int* in_sizes, int n_in,
                              void* d_out, int out_size)
{
    const float* x       = (const float*)d_in[0];
    const float* w_q     = (const float*)d_in[1];
    const float* w_kv    = (const float*)d_in[2];
    const float* w_dense = (const float*)d_in[3];
    float* out = (float*)d_out;

    float *qp, *kvp, *ctxp;
    __nv_bfloat16 *xh, *xl, *wqh, *wql, *wkvh, *wkvl, *wdh, *wdl, *ch, *cl;
    cudaGetSymbolAddress((void**)&qp,   g_q);
    cudaGetSymbolAddress((void**)&kvp,  g_kv);
    cudaGetSymbolAddress((void**)&ctxp, g_ctx);
    cudaGetSymbolAddress((void**)&xh,   g_xh);
    cudaGetSymbolAddress((void**)&xl,   g_xl);
    cudaGetSymbolAddress((void**)&wqh,  g_wqh);
    cudaGetSymbolAddress((void**)&wql,  g_wql);
    cudaGetSymbolAddress((void**)&wkvh, g_wkvh);
    cudaGetSymbolAddress((void**)&wkvl, g_wkvl);
    cudaGetSymbolAddress((void**)&wdh,  g_wdh);
    cudaGetSymbolAddress((void**)&wdl,  g_wdl);
    cudaGetSymbolAddress((void**)&ch,   g_ch);
    cudaGetSymbolAddress((void**)&cl,   g_cl);

    cudaFuncSetAttribute(gemm_mma, cudaFuncAttributeMaxDynamicSharedMemorySize, GEMM_SMEM);

    // prep: split x; transpose+split weights
    prep_split<<<(BSTOK * KDIM / 4 + 255) / 256, 256>>>(x, xh, xl, BSTOK * KDIM / 4);
    transpose_split<<<dim3(HID / 32, KDIM / 32), dim3(32, 8)>>>(w_q, wqh, wql, HID);
    transpose_split<<<dim3((2 * NG * DK) / 32, KDIM / 32), dim3(32, 8)>>>(w_kv, wkvh, wkvl, 2 * NG * DK);
    transpose_split<<<dim3(HID / 32, KDIM / 32), dim3(32, 8)>>>(w_dense, wdh, wdl, HID);

    // projections (mma.sync bf16x3)
    gemm_mma<<<dim3(HID / 128, BSTOK / 128), 256, GEMM_SMEM>>>(xh, xl, wqh, wql, qp, HID);
    gemm_mma<<<dim3((2 * NG * DK) / 128, BSTOK / 128), 256, GEMM_SMEM>>>(xh, xl, wkvh, wkvl, kvp, 2 * NG * DK);

    // rope
    rope_q_kernel<<<(BSTOK * NH * 64) / 256, 256>>>();
    rope_k_kernel<<<(BSTOK * NG * 64) / 256, 256>>>();

    // attention
    size_t smem = (size_t)(3 * QROWS * LDQ + QROWS * LDP) * sizeof(float);
    cudaFuncSetAttribute(flash_kernel, cudaFuncAttributeMaxDynamicSharedMemorySize, (int)smem);
    flash_kernel<<<dim3(SS / QROWS, NH, BB), 256, smem>>>();

    // dense projection (split ctx, mma.sync bf16x3)
    prep_split<<<(BSTOK * KDIM / 4 + 255) / 256, 256>>>(ctxp, ch, cl, BSTOK * KDIM / 4);
    gemm_mma<<<dim3(HID / 128, BSTOK / 128), 256, GEMM_SMEM>>>(ch, cl, wdh, wdl, out, HID);
}

// round 6
// speedup vs baseline: 3.5921x; 2.3872x over previous
#include <cuda_runtime.h>
#include <cuda_bf16.h>
#include <cstdint>
#include <math.h>

#define BB    2
#define SS    2048
#define HID   2048
#define NH    16
#define NG    4
#define DK    128
#define NHPG  4
#define BSTOK (BB*SS)
#define KDIM  2048

// ---------------------------------------------------------------------------
// Scratch (__device__ globals; allocation-free rule)
// ---------------------------------------------------------------------------
static __device__ float g_q  [BSTOK * HID];            // Q proj fp32
static __device__ float g_kv [BSTOK * 2 * NG * DK];    // K|V proj fp32

static __device__ __nv_bfloat16 g_xh [BSTOK * KDIM];
static __device__ __nv_bfloat16 g_xl [BSTOK * KDIM];
static __device__ __nv_bfloat16 g_wqh [HID * KDIM];
static __device__ __nv_bfloat16 g_wql [HID * KDIM];
static __device__ __nv_bfloat16 g_wkvh[(2*NG*DK) * KDIM];
static __device__ __nv_bfloat16 g_wkvl[(2*NG*DK) * KDIM];
static __device__ __nv_bfloat16 g_wdh [HID * KDIM];
static __device__ __nv_bfloat16 g_wdl [HID * KDIM];

static __device__ __nv_bfloat16 g_qh [BSTOK * HID];    // rope'd, pre-scaled Q hi/lo
static __device__ __nv_bfloat16 g_ql [BSTOK * HID];
static __device__ __nv_bfloat16 g_kh [BSTOK * NG * DK];// rope'd K hi/lo  [tok][g*128+d]
static __device__ __nv_bfloat16 g_kl [BSTOK * NG * DK];
static __device__ __nv_bfloat16 g_vth[BB * NG * DK * SS]; // V transposed [b,g][d][s]
static __device__ __nv_bfloat16 g_vtl[BB * NG * DK * SS];
static __device__ __nv_bfloat16 g_ch [BSTOK * KDIM];   // ctx hi/lo
static __device__ __nv_bfloat16 g_cl [BSTOK * KDIM];

// ---------------------------------------------------------------------------
// helpers (base-target safe)
// ---------------------------------------------------------------------------
__device__ __forceinline__ void cp_async16(uint32_t s, const void* g) {
    asm volatile("cp.async.cg.shared.global [%0], [%1], 16;\n" :: "r"(s), "l"(g) : "memory");
}
__device__ __forceinline__ void cp_commit() {
    asm volatile("cp.async.commit_group;\n" ::: "memory");
}
__device__ __forceinline__ uint32_t lds_u32(uint32_t a) {
    uint32_t v; asm("ld.shared.b32 %0, [%1];" : "=r"(v) : "r"(a)); return v;
}
__device__ __forceinline__ uint32_t packbf(float lo, float hi) {
    uint32_t d;
    asm("cvt.rn.bf16x2.f32 %0, %1, %2;" : "=r"(d) : "f"(hi), "f"(lo));
    return d;
}
__device__ __forceinline__ void mma16816(float* c, const uint32_t* a, const uint32_t* b)
{
    asm volatile(
        "mma.sync.aligned.m16n8k16.row.col.f32.bf16.bf16.f32 "
        "{%0,%1,%2,%3}, {%4,%5,%6,%7}, {%8,%9}, {%0,%1,%2,%3};"
        : "+f"(c[0]), "+f"(c[1]), "+f"(c[2]), "+f"(c[3])
        : "r"(a[0]), "r"(a[1]), "r"(a[2]), "r"(a[3]), "r"(b[0]), "r"(b[1]));
}

// ---------------------------------------------------------------------------
// Prep: fp32 -> (bf16 hi, bf16 lo) split
// ---------------------------------------------------------------------------
__global__ void prep_split(const float* __restrict__ src,
                           __nv_bfloat16* __restrict__ h,
                           __nv_bfloat16* __restrict__ l, int n4)
{
    int i = blockIdx.x * blockDim.x + threadIdx.x;
    if (i >= n4) return;
    float4 v = ((const float4*)src)[i];
    float vv[4] = {v.x, v.y, v.z, v.w};
    __nv_bfloat16 hh[4], ll[4];
#pragma unroll
    for (int j = 0; j < 4; j++) {
        hh[j] = __float2bfloat16_rn(vv[j]);
        ll[j] = __float2bfloat16_rn(vv[j] - __bfloat162float(hh[j]));
    }
    ((uint2*)h)[i] = *(uint2*)hh;
    ((uint2*)l)[i] = *(uint2*)ll;
}

// ---------------------------------------------------------------------------
// Prep: transpose W[K, N] fp32 -> WT hi/lo [N, K] bf16
// ---------------------------------------------------------------------------
__global__ void transpose_split(const float* __restrict__ W,
                                __nv_bfloat16* __restrict__ Th,
                                __nv_bfloat16* __restrict__ Tl, int Ncols)
{
    __shared__ float tile[32][33];
    int n = blockIdx.x * 32 + threadIdx.x;
    int k0 = blockIdx.y * 32;
#pragma unroll
    for (int r = 0; r < 4; r++) {
        int k = k0 + threadIdx.y + r * 8;
        tile[threadIdx.y + r * 8][threadIdx.x] = W[(size_t)k * Ncols + n];
    }
    __syncthreads();
#pragma unroll
    for (int r = 0; r < 4; r++) {
        int nn = blockIdx.x * 32 + threadIdx.y + r * 8;
        int kk = k0 + threadIdx.x;
        float v = tile[threadIdx.x][threadIdx.y + r * 8];
        __nv_bfloat16 hh = __float2bfloat16_rn(v);
        Th[(size_t)nn * KDIM + kk] = hh;
        Tl[(size_t)nn * KDIM + kk] = __float2bfloat16_rn(v - __bfloat162float(hh));
    }
}

// ---------------------------------------------------------------------------
// mma.sync GEMM (unchanged from R3): C = A @ B via bf16x3, fp32 accum
// ---------------------------------------------------------------------------
#define LDB    144
#define TILEB  (128 * LDB)
#define STAGEB (4 * TILEB)
#define GEMM_SMEM (2 * STAGEB)

__device__ __forceinline__ void load_chunk_mma(
    const __nv_bfloat16* __restrict__ Ah, const __nv_bfloat16* __restrict__ Al,
    const __nv_bfloat16* __restrict__ Bh, const __nv_bfloat16* __restrict__ Bl,
    int m0, int n0, int k0, uint32_t stage, int tid)
{
#pragma unroll
    for (int i = 0; i < 16; i++) {
        int lin = i * 256 + tid;
        int t   = lin >> 10;
        int rem = lin & 1023;
        int row = rem >> 3;
        int c   = rem & 7;
        const __nv_bfloat16* base = (t == 0) ? Ah : (t == 1) ? Al : (t == 2) ? Bh : Bl;
        int grow = ((t < 2) ? m0 : n0) + row;
        const __nv_bfloat16* gp = base + (size_t)grow * KDIM + k0 + c * 8;
        cp_async16(stage + t * TILEB + row * LDB + c * 16, gp);
    }
    cp_commit();
}

__global__ __launch_bounds__(256) void gemm_mma(
    const __nv_bfloat16* __restrict__ Ah, const __nv_bfloat16* __restrict__ Al,
    const __nv_bfloat16* __restrict__ Bh, const __nv_bfloat16* __restrict__ Bl,
    float* __restrict__ C, int N)
{
    extern __shared__ char smc[];
    uint32_t sb = (uint32_t)__cvta_generic_to_shared(smc);
    const int tid  = threadIdx.x;
    const int wid  = tid >> 5;
    const int lane = tid & 31;
    const int wm = wid >> 2;
    const int wn = wid & 3;
    const int m0 = blockIdx.y * 128;
    const int n0 = blockIdx.x * 128;
    const int r  = lane >> 2;
    const int kq = (lane & 3) * 2;

    float acc[4][4][4];
#pragma unroll
    for (int mt = 0; mt < 4; mt++)
#pragma unroll
        for (int nt = 0; nt < 4; nt++)
#pragma unroll
            for (int j = 0; j < 4; j++) acc[mt][nt][j] = 0.0f;

    const int NC = KDIM / 64;
    load_chunk_mma(Ah, Al, Bh, Bl, m0, n0, 0, sb, tid);

    for (int c = 0; c < NC; c++) {
        const uint32_t stg = sb + (uint32_t)(c & 1) * STAGEB;
        if (c + 1 < NC) {
            load_chunk_mma(Ah, Al, Bh, Bl, m0, n0, (c + 1) * 64,
                           sb + (uint32_t)((c + 1) & 1) * STAGEB, tid);
            asm volatile("cp.async.wait_group 1;\n" ::: "memory");
        } else {
            asm volatile("cp.async.wait_group 0;\n" ::: "memory");
        }
        __syncthreads();

        const char* sA  = smc + (stg - sb);
        const char* sAl = sA + TILEB;
        const char* sBh = sA + 2 * TILEB;
        const char* sBl = sA + 3 * TILEB;

#pragma unroll
        for (int ks = 0; ks < 4; ks++) {
            const int k0 = ks * 16;
            uint32_t ah[4][4], al[4][4], bh[4][2], bl[4][2];
#pragma unroll
            for (int mt = 0; mt < 4; mt++) {
                int row = wm * 64 + mt * 16 + r;
                ah[mt][0] = *(const uint32_t*)(sA  + (size_t)row       * LDB + (k0 + kq) * 2);
                ah[mt][1] = *(const uint32_t*)(sA  + (size_t)(row + 8) * LDB + (k0 + kq) * 2);
                ah[mt][2] = *(const uint32_t*)(sA  + (size_t)row       * LDB + (k0 + kq + 8) * 2);
                ah[mt][3] = *(const uint32_t*)(sA  + (size_t)(row + 8) * LDB + (k0 + kq + 8) * 2);
                al[mt][0] = *(const uint32_t*)(sAl + (size_t)row       * LDB + (k0 + kq) * 2);
                al[mt][1] = *(const uint32_t*)(sAl + (size_t)(row + 8) * LDB + (k0 + kq) * 2);
                al[mt][2] = *(const uint32_t*)(sAl + (size_t)row       * LDB + (k0 + kq + 8) * 2);
                al[mt][3] = *(const uint32_t*)(sAl + (size_t)(row + 8) * LDB + (k0 + kq + 8) * 2);
            }
#pragma unroll
            for (int nt = 0; nt < 4; nt++) {
                int nr = wn * 32 + nt * 8 + r;
                bh[nt][0] = *(const uint32_t*)(sBh + (size_t)nr * LDB + (k0 + kq) * 2);
                bh[nt][1] = *(const uint32_t*)(sBh + (size_t)nr * LDB + (k0 + kq + 8) * 2);
                bl[nt][0] = *(const uint32_t*)(sBl + (size_t)nr * LDB + (k0 + kq) * 2);
                bl[nt][1] = *(const uint32_t*)(sBl + (size_t)nr * LDB + (k0 + kq + 8) * 2);
            }
#pragma unroll
            for (int mt = 0; mt < 4; mt++)
#pragma unroll
                for (int nt = 0; nt < 4; nt++) {
                    mma16816(acc[mt][nt], ah[mt], bh[nt]);
                    mma16816(acc[mt][nt], ah[mt], bl[nt]);
                    mma16816(acc[mt][nt], al[mt], bh[nt]);
                }
        }
        __syncthreads();
    }

#pragma unroll
    for (int mt = 0; mt < 4; mt++) {
#pragma unroll
        for (int nt = 0; nt < 4; nt++) {
            int row = m0 + wm * 64 + mt * 16 + r;
            int col = n0 + wn * 32 + nt * 8 + kq;
            *(float2*)&C[(size_t)row * N + col]       = make_float2(acc[mt][nt][0], acc[mt][nt][1]);
            *(float2*)&C[(size_t)(row + 8) * N + col] = make_float2(acc[mt][nt][2], acc[mt][nt][3]);
        }
    }
}

// ---------------------------------------------------------------------------
// RoPE + scale + bf16 split (Q), RoPE + split (K), V transpose + split
// ---------------------------------------------------------------------------
#define QSCALE 0.08838834764831845f

__global__ void rope_split_q()
{
    int idx = blockIdx.x * blockDim.x + threadIdx.x;   // BSTOK*NH*64
    int j   = idx & 63;
    int h   = (idx >> 6) & (NH - 1);
    int tok = idx >> 10;
    if (tok >= BSTOK) return;
    int t = tok & (SS - 1);
    size_t base = (size_t)tok * HID + h * DK + j;
    float x1 = g_q[base], x2 = g_q[base + 64];
    float invf = exp2f(-0.20762050593045935f * (float)j);
    float f = (float)t * invf;
    float c, s;
    sincosf(f, &s, &c);
    float y1 = (x1 * c - x2 * s) * QSCALE;
    float y2 = (x2 * c + x1 * s) * QSCALE;
    __nv_bfloat16 h1 = __float2bfloat16_rn(y1);
    __nv_bfloat16 h2 = __float2bfloat16_rn(y2);
    g_qh[base]      = h1;
    g_qh[base + 64] = h2;
    g_ql[base]      = __float2bfloat16_rn(y1 - __bfloat162float(h1));
    g_ql[base + 64] = __float2bfloat16_rn(y2 - __bfloat162float(h2));
}

__global__ void rope_split_k()
{
    int idx = blockIdx.x * blockDim.x + threadIdx.x;   // BSTOK*NG*64
    int j   = idx & 63;
    int g   = (idx >> 6) & (NG - 1);
    int tok = idx >> 8;
    if (tok >= BSTOK) return;
    int t = tok & (SS - 1);
    size_t src = (size_t)tok * (2 * NG * DK) + g * DK + j;   // K half
    float x1 = g_kv[src], x2 = g_kv[src + 64];
    float invf = exp2f(-0.20762050593045935f * (float)j);
    float f = (float)t * invf;
    float c, s;
    sincosf(f, &s, &c);
    float y1 = x1 * c - x2 * s;
    float y2 = x2 * c + x1 * s;
    size_t dst = (size_t)tok * (NG * DK) + g * DK + j;
    __nv_bfloat16 h1 = __float2bfloat16_rn(y1);
    __nv_bfloat16 h2 = __float2bfloat16_rn(y2);
    g_kh[dst]      = h1;
    g_kh[dst + 64] = h2;
    g_kl[dst]      = __float2bfloat16_rn(y1 - __bfloat162float(h1));
    g_kl[dst + 64] = __float2bfloat16_rn(y2 - __bfloat162float(h2));
}

__global__ void split_vt()   // grid (SS/32, DK/32, BB*NG), block (32,8)
{
    __shared__ float tile[32][33];
    int bg = blockIdx.z;
    int b  = bg >> 2, g = bg & 3;
    int s0 = blockIdx.x * 32, d0 = blockIdx.y * 32;
#pragma unroll
    for (int r = 0; r < 4; r++) {
        int s = s0 + threadIdx.y + r * 8;
        tile[threadIdx.y + r * 8][threadIdx.x] =
            g_kv[(size_t)(b * SS + s) * (2 * NG * DK) + NG * DK + g * DK + d0 + threadIdx.x];
    }
    __syncthreads();
#pragma unroll
    for (int r = 0; r < 4; r++) {
        int d = d0 + threadIdx.y + r * 8;
        int s = s0 + threadIdx.x;
        float v = tile[threadIdx.x][threadIdx.y + r * 8];
        size_t dst = ((size_t)bg * DK + d) * SS + s;
        __nv_bfloat16 hh = __float2bfloat16_rn(v);
        g_vth[dst] = hh;
        g_vtl[dst] = __float2bfloat16_rn(v - __bfloat162float(hh));
    }
}

// ---------------------------------------------------------------------------
// Flash attention on mma.sync bf16 (x3 split both matmuls), causal.
// Block: 256 thr = 8 warps, each warp 16 query rows. 128 q x 64 k tiles.
// ---------------------------------------------------------------------------
#define FQT 128
#define FKT 64
// smem byte offsets (strides: Q/K rows 272B, Vt rows 144B)
#define OFF_QH 0
#define OFF_QL (FQT*272)                 // 34816
#define STG0   (2*FQT*272)               // 69632
#define STG_KH 0
#define STG_KL (FKT*272)                 // 17408
#define STG_VH (2*FKT*272)               // 34816
#define STG_VL (2*FKT*272 + FQT*144)     // 53248
#define STG_SZ (2*FKT*272 + 2*FQT*144)   // 71680
#define FLASH_SMEM (STG0 + 2*STG_SZ)     // 212992

__device__ __forceinline__ void flash_load_kv(int b, int g, int kbase, uint32_t stg, int tid)
{
#pragma unroll
    for (int i = 0; i < 16; i++) {
        int lin = i * 256 + tid;
        if (lin < 2048) {                 // K hi/lo tiles: 2 x 64 rows x 16 chunks
            int t   = lin >> 10;
            int rem = lin & 1023;
            int row = rem >> 4, c = rem & 15;
            const __nv_bfloat16* src = (t ? g_kl : g_kh)
                + (size_t)(b * SS + kbase + row) * (NG * DK) + g * DK + c * 8;
            cp_async16(stg + (t ? STG_KL : STG_KH) + row * 272 + c * 16, src);
        } else {                          // Vt hi/lo tiles: 2 x 128 rows x 8 chunks
            int lin2 = lin - 2048;
            int t   = lin2 >> 10;
            int rem = lin2 & 1023;
            int row = rem >> 3, c = rem & 7;
            const __nv_bfloat16* src = (t ? g_vtl : g_vth)
                + ((size_t)(b * NG + g) * DK + row) * SS + kbase + c * 8;
            cp_async16(stg + (t ? STG_VL : STG_VH) + row * 144 + c * 16, src);
        }
    }
    cp_commit();
}

__global__ __launch_bounds__(256) void flash_tc()
{
    extern __shared__ char smc[];
    uint32_t sb = (uint32_t)__cvta_generic_to_shared(smc);
    const int tid  = threadIdx.x;
    const int wid  = tid >> 5;
    const int lane = tid & 31;
    const int qt = gridDim.x - 1 - blockIdx.x;    // heavy tiles first
    const int h  = blockIdx.y;
    const int b  = blockIdx.z;
    const int g  = h / NHPG;
    const int q0 = qt * FQT;
    const int r  = lane >> 2;
    const int kq = (lane & 3) * 2;

    // load Q hi/lo tile (once)
#pragma unroll
    for (int i = 0; i < 16; i++) {
        int lin = i * 256 + tid;                  // 0..4095
        int t   = lin >> 11;
        int rem = lin & 2047;
        int row = rem >> 4, c = rem & 15;
        const __nv_bfloat16* src = (t ? g_ql : g_qh)
            + (size_t)(b * SS + q0 + row) * HID + h * DK + c * 8;
        cp_async16(sb + (t ? OFF_QL : OFF_QH) + row * 272 + c * 16, src);
    }
    cp_commit();

    const int numc = 2 * (qt + 1);
    flash_load_kv(b, g, 0, sb + STG0, tid);

    float m0 = -1e30f, m1 = -1e30f, l0 = 0.0f, l1 = 0.0f;
    float acc[16][4];
#pragma unroll
    for (int nt2 = 0; nt2 < 16; nt2++)
#pragma unroll
        for (int j = 0; j < 4; j++) acc[nt2][j] = 0.0f;

    const uint32_t qh_base = sb + OFF_QH + (wid * 16 + r) * 272 + kq * 2;

    for (int kc = 0; kc < numc; kc++) {
        const uint32_t stg = sb + STG0 + (uint32_t)(kc & 1) * STG_SZ;
        const int kbase = kc * FKT;
        if (kc + 1 < numc) {
            flash_load_kv(b, g, (kc + 1) * FKT, sb + STG0 + (uint32_t)((kc + 1) & 1) * STG_SZ, tid);
            asm volatile("cp.async.wait_group 1;\n" ::: "memory");
        } else {
            asm volatile("cp.async.wait_group 0;\n" ::: "memory");
        }
        __syncthreads();

        // ---- S = Q K^T (x3 split) ----
        float sc[8][4];
#pragma unroll
        for (int nt = 0; nt < 8; nt++)
#pragma unroll
            for (int j = 0; j < 4; j++) sc[nt][j] = 0.0f;

#pragma unroll
        for (int kd = 0; kd < 8; kd++) {
            uint32_t ah[4], al[4];
            uint32_t qa = qh_base + kd * 32;
            ah[0] = lds_u32(qa);
            ah[1] = lds_u32(qa + 8 * 272);
            ah[2] = lds_u32(qa + 16);
            ah[3] = lds_u32(qa + 8 * 272 + 16);
            qa += (OFF_QL - OFF_QH);
            al[0] = lds_u32(qa);
            al[1] = lds_u32(qa + 8 * 272);
            al[2] = lds_u32(qa + 16);
            al[3] = lds_u32(qa + 8 * 272 + 16);
#pragma unroll
            for (int nt = 0; nt < 8; nt++) {
                uint32_t kb = stg + STG_KH + (nt * 8 + r) * 272 + kq * 2 + kd * 32;
                uint32_t bh[2] = {lds_u32(kb), lds_u32(kb + 16)};
                uint32_t kbl = kb + (STG_KL - STG_KH);
                uint32_t bl[2] = {lds_u32(kbl), lds_u32(kbl + 16)};
                mma16816(sc[nt], ah, bh);
                mma16816(sc[nt], ah, bl);
                mma16816(sc[nt], al, bh);
            }
        }

        // ---- causal mask (only near-diagonal chunks) ----
        if (kbase + FKT > q0) {
            const int row0g = q0 + wid * 16 + r;
#pragma unroll
            for (int nt = 0; nt < 8; nt++) {
                int key = kbase + nt * 8 + kq;
                if (key     > row0g)     sc[nt][0] = -1e30f;
                if (key + 1 > row0g)     sc[nt][1] = -1e30f;
                if (key     > row0g + 8) sc[nt][2] = -1e30f;
                if (key + 1 > row0g + 8) sc[nt][3] = -1e30f;
            }
        }

        // ---- online softmax ----
        float mx0 = -1e30f, mx1 = -1e30f;
#pragma unroll
        for (int nt = 0; nt < 8; nt++) {
            mx0 = fmaxf(mx0, fmaxf(sc[nt][0], sc[nt][1]));
            mx1 = fmaxf(mx1, fmaxf(sc[nt][2], sc[nt][3]));
        }
        mx0 = fmaxf(mx0, __shfl_xor_sync(0xffffffffu, mx0, 1));
        mx0 = fmaxf(mx0, __shfl_xor_sync(0xffffffffu, mx0, 2));
        mx1 = fmaxf(mx1, __shfl_xor_sync(0xffffffffu, mx1, 1));
        mx1 = fmaxf(mx1, __shfl_xor_sync(0xffffffffu, mx1, 2));
        float mn0 = fmaxf(m0, mx0), mn1 = fmaxf(m1, mx1);
        float c0 = __expf(m0 - mn0), c1 = __expf(m1 - mn1);
        float sum0 = 0.0f, sum1 = 0.0f;
#pragma unroll
        for (int nt = 0; nt < 8; nt++) {
            sc[nt][0] = __expf(sc[nt][0] - mn0); sum0 += sc[nt][0];
            sc[nt][1] = __expf(sc[nt][1] - mn0); sum0 += sc[nt][1];
            sc[nt][2] = __expf(sc[nt][2] - mn1); sum1 += sc[nt][2];
            sc[nt][3] = __expf(sc[nt][3] - mn1); sum1 += sc[nt][3];
        }
        sum0 += __shfl_xor_sync(0xffffffffu, sum0, 1);
        sum0 += __shfl_xor_sync(0xffffffffu, sum0, 2);
        sum1 += __shfl_xor_sync(0xffffffffu, sum1, 1);
        sum1 += __shfl_xor_sync(0xffffffffu, sum1, 2);
        l0 = l0 * c0 + sum0;  m0 = mn0;
        l1 = l1 * c1 + sum1;  m1 = mn1;
#pragma unroll
        for (int nt2 = 0; nt2 < 16; nt2++) {
            acc[nt2][0] *= c0; acc[nt2][1] *= c0;
            acc[nt2][2] *= c1; acc[nt2][3] *= c1;
        }

        // ---- O += P V (x3 split; P frags straight from accumulators) ----
#pragma unroll
        for (int kk = 0; kk < 4; kk++) {
            uint32_t ph[4], pl[4];
#pragma unroll
            for (int t4 = 0; t4 < 4; t4++) {
                int nt = 2 * kk + (t4 >> 1);
                float lo = sc[nt][(t4 & 1) * 2];
                float hi = sc[nt][(t4 & 1) * 2 + 1];
                uint32_t w = packbf(lo, hi);
                ph[t4] = w;
                float rlo = lo - __uint_as_float(w << 16);
                float rhi = hi - __uint_as_float(w & 0xffff0000u);
                pl[t4] = packbf(rlo, rhi);
            }
#pragma unroll
            for (int nt2 = 0; nt2 < 16; nt2++) {
                uint32_t vb = stg + STG_VH + (nt2 * 8 + r) * 144 + (kk * 16 + kq) * 2;
                uint32_t bh[2] = {lds_u32(vb), lds_u32(vb + 16)};
                uint32_t vbl = vb + (STG_VL - STG_VH);
                uint32_t bl[2] = {lds_u32(vbl), lds_u32(vbl + 16)};
                mma16816(acc[nt2], ph, bh);
                mma16816(acc[nt2], ph, bl);
                mma16816(acc[nt2], pl, bh);
            }
        }
        __syncthreads();
    }

    // ---- epilogue: normalize and write ctx hi/lo splits ----
    float inv0 = 1.0f / l0, inv1 = 1.0f / l1;
    size_t row0 = (size_t)(b * SS + q0 + wid * 16 + r);
    size_t row1 = row0 + 8;
#pragma unroll
    for (int nt2 = 0; nt2 < 16; nt2++) {
        int d = h * DK + nt2 * 8 + kq;
        float o0 = acc[nt2][0] * inv0, o1 = acc[nt2][1] * inv0;
        uint32_t wh = packbf(o0, o1);
        uint32_t wl = packbf(o0 - __uint_as_float(wh << 16),
                             o1 - __uint_as_float(wh & 0xffff0000u));
        *(uint32_t*)&g_ch[row0 * HID + d] = wh;
        *(uint32_t*)&g_cl[row0 * HID + d] = wl;
        float o2 = acc[nt2][2] * inv1, o3 = acc[nt2][3] * inv1;
        wh = packbf(o2, o3);
        wl = packbf(o2 - __uint_as_float(wh << 16),
                    o3 - __uint_as_float(wh & 0xffff0000u));
        *(uint32_t*)&g_ch[row1 * HID + d] = wh;
        *(uint32_t*)&g_cl[row1 * HID + d] = wl;
    }
}

// ---------------------------------------------------------------------------
extern "C" void kernel_launch(void* const* d_in, const int* in_sizes, int n_in,
                              void* d_out, int out_size)
{
    const float* x       = (const float*)d_in[0];
    const float* w_q     = (const float*)d_in[1];
    const float* w_kv    = (const float*)d_in[2];
    const float* w_dense = (const float*)d_in[3];
    float* out = (float*)d_out;

    float *qp, *kvp;
    __nv_bfloat16 *xh, *xl, *wqh, *wql, *wkvh, *wkvl, *wdh, *wdl, *ch, *cl;
    cudaGetSymbolAddress((void**)&qp,   g_q);
    cudaGetSymbolAddress((void**)&kvp,  g_kv);
    cudaGetSymbolAddress((void**)&xh,   g_xh);
    cudaGetSymbolAddress((void**)&xl,   g_xl);
    cudaGetSymbolAddress((void**)&wqh,  g_wqh);
    cudaGetSymbolAddress((void**)&wql,  g_wql);
    cudaGetSymbolAddress((void**)&wkvh, g_wkvh);
    cudaGetSymbolAddress((void**)&wkvl, g_wkvl);
    cudaGetSymbolAddress((void**)&wdh,  g_wdh);
    cudaGetSymbolAddress((void**)&wdl,  g_wdl);
    cudaGetSymbolAddress((void**)&ch,   g_ch);
    cudaGetSymbolAddress((void**)&cl,   g_cl);

    cudaFuncSetAttribute(gemm_mma, cudaFuncAttributeMaxDynamicSharedMemorySize, GEMM_SMEM);
    cudaFuncSetAttribute(flash_tc, cudaFuncAttributeMaxDynamicSharedMemorySize, FLASH_SMEM);

    // prep: split x; transpose+split weights
    prep_split<<<(BSTOK * KDIM / 4 + 255) / 256, 256>>>(x, xh, xl, BSTOK * KDIM / 4);
    transpose_split<<<dim3(HID / 32, KDIM / 32), dim3(32, 8)>>>(w_q, wqh, wql, HID);
    transpose_split<<<dim3((2 * NG * DK) / 32, KDIM / 32), dim3(32, 8)>>>(w_kv, wkvh, wkvl, 2 * NG * DK);
    transpose_split<<<dim3(HID / 32, KDIM / 32), dim3(32, 8)>>>(w_dense, wdh, wdl, HID);

    // projections
    gemm_mma<<<dim3(HID / 128, BSTOK / 128), 256, GEMM_SMEM>>>(xh, xl, wqh, wql, qp, HID);
    gemm_mma<<<dim3((2 * NG * DK) / 128, BSTOK / 128), 256, GEMM_SMEM>>>(xh, xl, wkvh, wkvl, kvp, 2 * NG * DK);

    // rope + splits + V transpose
    rope_split_q<<<(BSTOK * NH * 64) / 256, 256>>>();
    rope_split_k<<<(BSTOK * NG * 64) / 256, 256>>>();
    split_vt<<<dim3(SS / 32, DK / 32, BB * NG), dim3(32, 8)>>>();

    // attention (tensor cores)
    flash_tc<<<dim3(SS / FQT, NH, BB), 256, FLASH_SMEM>>>();

    // dense projection
    gemm_mma<<<dim3(HID / 128, BSTOK / 128), 256, GEMM_SMEM>>>(ch, cl, wdh, wdl, out, HID);
}

// round 8
// speedup vs baseline: 3.7051x; 1.0314x over previous
#include <cuda_runtime.h>
#include <cuda_bf16.h>
#include <cstdint>
#include <math.h>

#define BB    2
#define SS    2048
#define HID   2048
#define NH    16
#define NG    4
#define DK    128
#define NHPG  4
#define BSTOK (BB*SS)
#define KDIM  2048

// ---------------------------------------------------------------------------
// Scratch (__device__ globals; allocation-free rule)
// ---------------------------------------------------------------------------
static __device__ float g_q  [BSTOK * HID];            // Q proj fp32
static __device__ float g_kv [BSTOK * 2 * NG * DK];    // K|V proj fp32

static __device__ __nv_bfloat16 g_xh [BSTOK * KDIM];
static __device__ __nv_bfloat16 g_xl [BSTOK * KDIM];
static __device__ __nv_bfloat16 g_wqh [HID * KDIM];
static __device__ __nv_bfloat16 g_wql [HID * KDIM];
static __device__ __nv_bfloat16 g_wkvh[(2*NG*DK) * KDIM];
static __device__ __nv_bfloat16 g_wkvl[(2*NG*DK) * KDIM];
static __device__ __nv_bfloat16 g_wdh [HID * KDIM];
static __device__ __nv_bfloat16 g_wdl [HID * KDIM];

static __device__ __nv_bfloat16 g_qh [BSTOK * HID];    // rope'd, pre-scaled Q hi/lo
static __device__ __nv_bfloat16 g_ql [BSTOK * HID];
static __device__ __nv_bfloat16 g_kh [BSTOK * NG * DK];// rope'd K hi/lo
static __device__ __nv_bfloat16 g_kl [BSTOK * NG * DK];
static __device__ __nv_bfloat16 g_vth[BB * NG * DK * SS]; // V transposed [b,g][d][s]
static __device__ __nv_bfloat16 g_vtl[BB * NG * DK * SS];
static __device__ __nv_bfloat16 g_ch [BSTOK * KDIM];   // ctx hi/lo
static __device__ __nv_bfloat16 g_cl [BSTOK * KDIM];

// ---------------------------------------------------------------------------
// helpers (base-target safe)
// ---------------------------------------------------------------------------
__device__ __forceinline__ void cp_async16(uint32_t s, const void* g) {
    asm volatile("cp.async.cg.shared.global [%0], [%1], 16;\n" :: "r"(s), "l"(g) : "memory");
}
__device__ __forceinline__ void cp_commit() {
    asm volatile("cp.async.commit_group;\n" ::: "memory");
}
__device__ __forceinline__ uint32_t lds_u32(uint32_t a) {
    uint32_t v; asm("ld.shared.b32 %0, [%1];" : "=r"(v) : "r"(a)); return v;
}
__device__ __forceinline__ void ldsm4(uint32_t* r, uint32_t a) {
    asm volatile("ldmatrix.sync.aligned.m8n8.x4.shared.b16 {%0,%1,%2,%3}, [%4];"
        : "=r"(r[0]), "=r"(r[1]), "=r"(r[2]), "=r"(r[3]) : "r"(a));
}
__device__ __forceinline__ uint32_t packbf(float lo, float hi) {
    uint32_t d;
    asm("cvt.rn.bf16x2.f32 %0, %1, %2;" : "=r"(d) : "f"(hi), "f"(lo));
    return d;
}
__device__ __forceinline__ void mma16816(float* c, const uint32_t* a, const uint32_t* b)
{
    asm volatile(
        "mma.sync.aligned.m16n8k16.row.col.f32.bf16.bf16.f32 "
        "{%0,%1,%2,%3}, {%4,%5,%6,%7}, {%8,%9}, {%0,%1,%2,%3};"
        : "+f"(c[0]), "+f"(c[1]), "+f"(c[2]), "+f"(c[3])
        : "r"(a[0]), "r"(a[1]), "r"(a[2]), "r"(a[3]), "r"(b[0]), "r"(b[1]));
}

// ---------------------------------------------------------------------------
// Prep: fp32 -> (bf16 hi, bf16 lo) split
// ---------------------------------------------------------------------------
__global__ void prep_split(const float* __restrict__ src,
                           __nv_bfloat16* __restrict__ h,
                           __nv_bfloat16* __restrict__ l, int n4)
{
    int i = blockIdx.x * blockDim.x + threadIdx.x;
    if (i >= n4) return;
    float4 v = ((const float4*)src)[i];
    float vv[4] = {v.x, v.y, v.z, v.w};
    __nv_bfloat16 hh[4], ll[4];
#pragma unroll
    for (int j = 0; j < 4; j++) {
        hh[j] = __float2bfloat16_rn(vv[j]);
        ll[j] = __float2bfloat16_rn(vv[j] - __bfloat162float(hh[j]));
    }
    ((uint2*)h)[i] = *(uint2*)hh;
    ((uint2*)l)[i] = *(uint2*)ll;
}

// ---------------------------------------------------------------------------
// Prep: transpose W[K, N] fp32 -> WT hi/lo [N, K] bf16
// ---------------------------------------------------------------------------
__global__ void transpose_split(const float* __restrict__ W,
                                __nv_bfloat16* __restrict__ Th,
                                __nv_bfloat16* __restrict__ Tl, int Ncols)
{
    __shared__ float tile[32][33];
    int n = blockIdx.x * 32 + threadIdx.x;
    int k0 = blockIdx.y * 32;
#pragma unroll
    for (int r = 0; r < 4; r++) {
        int k = k0 + threadIdx.y + r * 8;
        tile[threadIdx.y + r * 8][threadIdx.x] = W[(size_t)k * Ncols + n];
    }
    __syncthreads();
#pragma unroll
    for (int r = 0; r < 4; r++) {
        int nn = blockIdx.x * 32 + threadIdx.y + r * 8;
        int kk = k0 + threadIdx.x;
        float v = tile[threadIdx.x][threadIdx.y + r * 8];
        __nv_bfloat16 hh = __float2bfloat16_rn(v);
        Th[(size_t)nn * KDIM + kk] = hh;
        Tl[(size_t)nn * KDIM + kk] = __float2bfloat16_rn(v - __bfloat162float(hh));
    }
}

// ---------------------------------------------------------------------------
// mma.sync GEMM: C = A @ B via bf16x3, fp32 accum. ldmatrix + 3-stage cp.async.
// Tile 128x128, 8 warps (2M x 4N), warp tile 64x32.
// ---------------------------------------------------------------------------
#define LDB    144
#define TILEB  (128 * LDB)
#define STAGEB (4 * TILEB)
#define GEMM_SMEM (3 * STAGEB)     // 221184 B

__device__ __forceinline__ void load_chunk_mma(
    const __nv_bfloat16* __restrict__ Ah, const __nv_bfloat16* __restrict__ Al,
    const __nv_bfloat16* __restrict__ Bh, const __nv_bfloat16* __restrict__ Bl,
    int m0, int n0, int k0, uint32_t stage, int tid)
{
#pragma unroll
    for (int i = 0; i < 16; i++) {
        int lin = i * 256 + tid;
        int t   = lin >> 10;
        int rem = lin & 1023;
        int row = rem >> 3;
        int c   = rem & 7;
        const __nv_bfloat16* base = (t == 0) ? Ah : (t == 1) ? Al : (t == 2) ? Bh : Bl;
        int grow = ((t < 2) ? m0 : n0) + row;
        const __nv_bfloat16* gp = base + (size_t)grow * KDIM + k0 + c * 8;
        cp_async16(stage + t * TILEB + row * LDB + c * 16, gp);
    }
    cp_commit();
}

__global__ __launch_bounds__(256) void gemm_mma(
    const __nv_bfloat16* __restrict__ Ah, const __nv_bfloat16* __restrict__ Al,
    const __nv_bfloat16* __restrict__ Bh, const __nv_bfloat16* __restrict__ Bl,
    float* __restrict__ C, int N)
{
    extern __shared__ char smc[];
    uint32_t sb = (uint32_t)__cvta_generic_to_shared(smc);
    const int tid  = threadIdx.x;
    const int wid  = tid >> 5;
    const int lane = tid & 31;
    const int wm = wid >> 2;
    const int wn = wid & 3;
    const int m0 = blockIdx.y * 128;
    const int n0 = blockIdx.x * 128;
    const int r  = lane >> 2;           // epilogue row
    const int kq = (lane & 3) * 2;      // epilogue col pair

    // ldmatrix lane addressing
    const int qd = lane >> 3, lr = lane & 7;
    const uint32_t aBase = (uint32_t)((wm * 64 + (qd & 1) * 8 + lr) * LDB + (qd >> 1) * 16);
    const uint32_t bBase = (uint32_t)((wn * 32 + (qd >> 1) * 8 + lr) * LDB + (qd & 1) * 16);

    float acc[4][4][4];
#pragma unroll
    for (int mt = 0; mt < 4; mt++)
#pragma unroll
        for (int nt = 0; nt < 4; nt++)
#pragma unroll
            for (int j = 0; j < 4; j++) acc[mt][nt][j] = 0.0f;

    const int NC = KDIM / 64;           // 32
    load_chunk_mma(Ah, Al, Bh, Bl, m0, n0, 0, sb, tid);
    load_chunk_mma(Ah, Al, Bh, Bl, m0, n0, 64, sb + STAGEB, tid);

    for (int c = 0; c < NC; c++) {
        if (c + 1 < NC) {
            asm volatile("cp.async.wait_group 1;\n" ::: "memory");
        } else {
            asm volatile("cp.async.wait_group 0;\n" ::: "memory");
        }
        __syncthreads();
        if (c + 2 < NC)
            load_chunk_mma(Ah, Al, Bh, Bl, m0, n0, (c + 2) * 64,
                           sb + (uint32_t)((c + 2) % 3) * STAGEB, tid);

        const uint32_t stg = sb + (uint32_t)(c % 3) * STAGEB;

#pragma unroll
        for (int ks = 0; ks < 4; ks++) {
            const uint32_t koff = (uint32_t)ks * 32;
            uint32_t ah[4][4], al[4][4], bh[2][4], bl[2][4];
#pragma unroll
            for (int mt = 0; mt < 4; mt++)
                ldsm4(ah[mt], stg + aBase + (uint32_t)mt * (16 * LDB) + koff);
#pragma unroll
            for (int mt = 0; mt < 4; mt++)
                ldsm4(al[mt], stg + TILEB + aBase + (uint32_t)mt * (16 * LDB) + koff);
#pragma unroll
            for (int p = 0; p < 2; p++)
                ldsm4(bh[p], stg + 2 * TILEB + bBase + (uint32_t)p * (16 * LDB) + koff);
#pragma unroll
            for (int p = 0; p < 2; p++)
                ldsm4(bl[p], stg + 3 * TILEB + bBase + (uint32_t)p * (16 * LDB) + koff);

#pragma unroll
            for (int mt = 0; mt < 4; mt++)
#pragma unroll
                for (int nt = 0; nt < 4; nt++) {
                    const uint32_t* bhp = &bh[nt >> 1][(nt & 1) * 2];
                    const uint32_t* blp = &bl[nt >> 1][(nt & 1) * 2];
                    mma16816(acc[mt][nt], ah[mt], bhp);
                    mma16816(acc[mt][nt], ah[mt], blp);
                    mma16816(acc[mt][nt], al[mt], bhp);
                }
        }
    }

#pragma unroll
    for (int mt = 0; mt < 4; mt++) {
#pragma unroll
        for (int nt = 0; nt < 4; nt++) {
            int row = m0 + wm * 64 + mt * 16 + r;
            int col = n0 + wn * 32 + nt * 8 + kq;
            *(float2*)&C[(size_t)row * N + col]       = make_float2(acc[mt][nt][0], acc[mt][nt][1]);
            *(float2*)&C[(size_t)(row + 8) * N + col] = make_float2(acc[mt][nt][2], acc[mt][nt][3]);
        }
    }
}

// ---------------------------------------------------------------------------
// RoPE + scale + bf16 split (Q), RoPE + split (K), V transpose + split
// ---------------------------------------------------------------------------
#define QSCALE 0.08838834764831845f

__global__ void rope_split_q()
{
    int idx = blockIdx.x * blockDim.x + threadIdx.x;   // BSTOK*NH*64
    int j   = idx & 63;
    int h   = (idx >> 6) & (NH - 1);
    int tok = idx >> 10;
    if (tok >= BSTOK) return;
    int t = tok & (SS - 1);
    size_t base = (size_t)tok * HID + h * DK + j;
    float x1 = g_q[base], x2 = g_q[base + 64];
    float invf = exp2f(-0.20762050593045935f * (float)j);
    float f = (float)t * invf;
    float c, s;
    sincosf(f, &s, &c);
    float y1 = (x1 * c - x2 * s) * QSCALE;
    float y2 = (x2 * c + x1 * s) * QSCALE;
    __nv_bfloat16 h1 = __float2bfloat16_rn(y1);
    __nv_bfloat16 h2 = __float2bfloat16_rn(y2);
    g_qh[base]      = h1;
    g_qh[base + 64] = h2;
    g_ql[base]      = __float2bfloat16_rn(y1 - __bfloat162float(h1));
    g_ql[base + 64] = __float2bfloat16_rn(y2 - __bfloat162float(h2));
}

__global__ void rope_split_k()
{
    int idx = blockIdx.x * blockDim.x + threadIdx.x;   // BSTOK*NG*64
    int j   = idx & 63;
    int g   = (idx >> 6) & (NG - 1);
    int tok = idx >> 8;
    if (tok >= BSTOK) return;
    int t = tok & (SS - 1);
    size_t src = (size_t)tok * (2 * NG * DK) + g * DK + j;   // K half
    float x1 = g_kv[src], x2 = g_kv[src + 64];
    float invf = exp2f(-0.20762050593045935f * (float)j);
    float f = (float)t * invf;
    float c, s;
    sincosf(f, &s, &c);
    float y1 = x1 * c - x2 * s;
    float y2 = x2 * c + x1 * s;
    size_t dst = (size_t)tok * (NG * DK) + g * DK + j;
    __nv_bfloat16 h1 = __float2bfloat16_rn(y1);
    __nv_bfloat16 h2 = __float2bfloat16_rn(y2);
    g_kh[dst]      = h1;
    g_kh[dst + 64] = h2;
    g_kl[dst]      = __float2bfloat16_rn(y1 - __bfloat162float(h1));
    g_kl[dst + 64] = __float2bfloat16_rn(y2 - __bfloat162float(h2));
}

__global__ void split_vt()   // grid (SS/32, DK/32, BB*NG), block (32,8)
{
    __shared__ float tile[32][33];
    int bg = blockIdx.z;
    int b  = bg >> 2, g = bg & 3;
    int s0 = blockIdx.x * 32, d0 = blockIdx.y * 32;
#pragma unroll
    for (int r = 0; r < 4; r++) {
        int s = s0 + threadIdx.y + r * 8;
        tile[threadIdx.y + r * 8][threadIdx.x] =
            g_kv[(size_t)(b * SS + s) * (2 * NG * DK) + NG * DK + g * DK + d0 + threadIdx.x];
    }
    __syncthreads();
#pragma unroll
    for (int r = 0; r < 4; r++) {
        int d = d0 + threadIdx.y + r * 8;
        int s = s0 + threadIdx.x;
        float v = tile[threadIdx.x][threadIdx.y + r * 8];
        size_t dst = ((size_t)bg * DK + d) * SS + s;
        __nv_bfloat16 hh = __float2bfloat16_rn(v);
        g_vth[dst] = hh;
        g_vtl[dst] = __float2bfloat16_rn(v - __bfloat162float(hh));
    }
}

// ---------------------------------------------------------------------------
// Flash attention on mma.sync bf16 (x3 split both matmuls), causal.
// ---------------------------------------------------------------------------
#define FQT 128
#define FKT 64
#define OFF_QH 0
#define OFF_QL (FQT*272)
#define STG0   (2*FQT*272)
#define STG_KH 0
#define STG_KL (FKT*272)
#define STG_VH (2*FKT*272)
#define STG_VL (2*FKT*272 + FQT*144)
#define STG_SZ (2*FKT*272 + 2*FQT*144)
#define FLASH_SMEM (STG0 + 2*STG_SZ)

__device__ __forceinline__ void flash_load_kv(int b, int g, int kbase, uint32_t stg, int tid)
{
#pragma unroll
    for (int i = 0; i < 16; i++) {
        int lin = i * 256 + tid;
        if (lin < 2048) {
            int t   = lin >> 10;
            int rem = lin & 1023;
            int row = rem >> 4, c = rem & 15;
            const __nv_bfloat16* src = (t ? g_kl : g_kh)
                + (size_t)(b * SS + kbase + row) * (NG * DK) + g * DK + c * 8;
            cp_async16(stg + (t ? STG_KL : STG_KH) + row * 272 + c * 16, src);
        } else {
            int lin2 = lin - 2048;
            int t   = lin2 >> 10;
            int rem = lin2 & 1023;
            int row = rem >> 3, c = rem & 7;
            const __nv_bfloat16* src = (t ? g_vtl : g_vth)
                + ((size_t)(b * NG + g) * DK + row) * SS + kbase + c * 8;
            cp_async16(stg + (t ? STG_VL : STG_VH) + row * 144 + c * 16, src);
        }
    }
    cp_commit();
}

__global__ __launch_bounds__(256) void flash_tc()
{
    extern __shared__ char smc[];
    uint32_t sb = (uint32_t)__cvta_generic_to_shared(smc);
    const int tid  = threadIdx.x;
    const int wid  = tid >> 5;
    const int lane = tid & 31;
    const int qt = gridDim.x - 1 - blockIdx.x;
    const int h  = blockIdx.y;
    const int b  = blockIdx.z;
    const int g  = h / NHPG;
    const int q0 = qt * FQT;
    const int r  = lane >> 2;
    const int kq = (lane & 3) * 2;

#pragma unroll
    for (int i = 0; i < 16; i++) {
        int lin = i * 256 + tid;
        int t   = lin >> 11;
        int rem = lin & 2047;
        int row = rem >> 4, c = rem & 15;
        const __nv_bfloat16* src = (t ? g_ql : g_qh)
            + (size_t)(b * SS + q0 + row) * HID + h * DK + c * 8;
        cp_async16(sb + (t ? OFF_QL : OFF_QH) + row * 272 + c * 16, src);
    }
    cp_commit();

    const int numc = 2 * (qt + 1);
    flash_load_kv(b, g, 0, sb + STG0, tid);

    float m0 = -1e30f, m1 = -1e30f, l0 = 0.0f, l1 = 0.0f;
    float acc[16][4];
#pragma unroll
    for (int nt2 = 0; nt2 < 16; nt2++)
#pragma unroll
        for (int j = 0; j < 4; j++) acc[nt2][j] = 0.0f;

    const uint32_t qh_base = sb + OFF_QH + (wid * 16 + r) * 272 + kq * 2;

    for (int kc = 0; kc < numc; kc++) {
        const uint32_t stg = sb + STG0 + (uint32_t)(kc & 1) * STG_SZ;
        const int kbase = kc * FKT;
        if (kc + 1 < numc) {
            flash_load_kv(b, g, (kc + 1) * FKT, sb + STG0 + (uint32_t)((kc + 1) & 1) * STG_SZ, tid);
            asm volatile("cp.async.wait_group 1;\n" ::: "memory");
        } else {
            asm volatile("cp.async.wait_group 0;\n" ::: "memory");
        }
        __syncthreads();

        float sc[8][4];
#pragma unroll
        for (int nt = 0; nt < 8; nt++)
#pragma unroll
            for (int j = 0; j < 4; j++) sc[nt][j] = 0.0f;

#pragma unroll
        for (int kd = 0; kd < 8; kd++) {
            uint32_t ah[4], al[4];
            uint32_t qa = qh_base + kd * 32;
            ah[0] = lds_u32(qa);
            ah[1] = lds_u32(qa + 8 * 272);
            ah[2] = lds_u32(qa + 16);
            ah[3] = lds_u32(qa + 8 * 272 + 16);
            qa += (OFF_QL - OFF_QH);
            al[0] = lds_u32(qa);
            al[1] = lds_u32(qa + 8 * 272);
            al[2] = lds_u32(qa + 16);
            al[3] = lds_u32(qa + 8 * 272 + 16);
#pragma unroll
            for (int nt = 0; nt < 8; nt++) {
                uint32_t kb = stg + STG_KH + (nt * 8 + r) * 272 + kq * 2 + kd * 32;
                uint32_t bh[2] = {lds_u32(kb), lds_u32(kb + 16)};
                uint32_t kbl = kb + (STG_KL - STG_KH);
                uint32_t bl[2] = {lds_u32(kbl), lds_u32(kbl + 16)};
                mma16816(sc[nt], ah, bh);
                mma16816(sc[nt], ah, bl);
                mma16816(sc[nt], al, bh);
            }
        }

        if (kbase + FKT > q0) {
            const int row0g = q0 + wid * 16 + r;
#pragma unroll
            for (int nt = 0; nt < 8; nt++) {
                int key = kbase + nt * 8 + kq;
                if (key     > row0g)     sc[nt][0] = -1e30f;
                if (key + 1 > row0g)     sc[nt][1] = -1e30f;
                if (key     > row0g + 8) sc[nt][2] = -1e30f;
                if (key + 1 > row0g + 8) sc[nt][3] = -1e30f;
            }
        }

        float mx0 = -1e30f, mx1 = -1e30f;
#pragma unroll
        for (int nt = 0; nt < 8; nt++) {
            mx0 = fmaxf(mx0, fmaxf(sc[nt][0], sc[nt][1]));
            mx1 = fmaxf(mx1, fmaxf(sc[nt][2], sc[nt][3]));
        }
        mx0 = fmaxf(mx0, __shfl_xor_sync(0xffffffffu, mx0, 1));
        mx0 = fmaxf(mx0, __shfl_xor_sync(0xffffffffu, mx0, 2));
        mx1 = fmaxf(mx1, __shfl_xor_sync(0xffffffffu, mx1, 1));
        mx1 = fmaxf(mx1, __shfl_xor_sync(0xffffffffu, mx1, 2));
        float mn0 = fmaxf(m0, mx0), mn1 = fmaxf(m1, mx1);
        float c0 = __expf(m0 - mn0), c1 = __expf(m1 - mn1);
        float sum0 = 0.0f, sum1 = 0.0f;
#pragma unroll
        for (int nt = 0; nt < 8; nt++) {
            sc[nt][0] = __expf(sc[nt][0] - mn0); sum0 += sc[nt][0];
            sc[nt][1] = __expf(sc[nt][1] - mn0); sum0 += sc[nt][1];
            sc[nt][2] = __expf(sc[nt][2] - mn1); sum1 += sc[nt][2];
            sc[nt][3] = __expf(sc[nt][3] - mn1); sum1 += sc[nt][3];
        }
        sum0 += __shfl_xor_sync(0xffffffffu, sum0, 1);
        sum0 += __shfl_xor_sync(0xffffffffu, sum0, 2);
        sum1 += __shfl_xor_sync(0xffffffffu, sum1, 1);
        sum1 += __shfl_xor_sync(0xffffffffu, sum1, 2);
        l0 = l0 * c0 + sum0;  m0 = mn0;
        l1 = l1 * c1 + sum1;  m1 = mn1;
#pragma unroll
        for (int nt2 = 0; nt2 < 16; nt2++) {
            acc[nt2][0] *= c0; acc[nt2][1] *= c0;
            acc[nt2][2] *= c1; acc[nt2][3] *= c1;
        }

#pragma unroll
        for (int kk = 0; kk < 4; kk++) {
            uint32_t ph[4], pl[4];
#pragma unroll
            for (int t4 = 0; t4 < 4; t4++) {
                int nt = 2 * kk + (t4 >> 1);
                float lo = sc[nt][(t4 & 1) * 2];
                float hi = sc[nt][(t4 & 1) * 2 + 1];
                uint32_t w = packbf(lo, hi);
                ph[t4] = w;
                float rlo = lo - __uint_as_float(w << 16);
                float rhi = hi - __uint_as_float(w & 0xffff0000u);
                pl[t4] = packbf(rlo, rhi);
            }
#pragma unroll
            for (int nt2 = 0; nt2 < 16; nt2++) {
                uint32_t vb = stg + STG_VH + (nt2 * 8 + r) * 144 + (kk * 16 + kq) * 2;
                uint32_t bh[2] = {lds_u32(vb), lds_u32(vb + 16)};
                uint32_t vbl = vb + (STG_VL - STG_VH);
                uint32_t bl[2] = {lds_u32(vbl), lds_u32(vbl + 16)};
                mma16816(acc[nt2], ph, bh);
                mma16816(acc[nt2], ph, bl);
                mma16816(acc[nt2], pl, bh);
            }
        }
        __syncthreads();
    }

    float inv0 = 1.0f / l0, inv1 = 1.0f / l1;
    size_t row0 = (size_t)(b * SS + q0 + wid * 16 + r);
    size_t row1 = row0 + 8;
#pragma unroll
    for (int nt2 = 0; nt2 < 16; nt2++) {
        int d = h * DK + nt2 * 8 + kq;
        float o0 = acc[nt2][0] * inv0, o1 = acc[nt2][1] * inv0;
        uint32_t wh = packbf(o0, o1);
        uint32_t wl = packbf(o0 - __uint_as_float(wh << 16),
                             o1 - __uint_as_float(wh & 0xffff0000u));
        *(uint32_t*)&g_ch[row0 * HID + d] = wh;
        *(uint32_t*)&g_cl[row0 * HID + d] = wl;
        float o2 = acc[nt2][2] * inv1, o3 = acc[nt2][3] * inv1;
        wh = packbf(o2, o3);
        wl = packbf(o2 - __uint_as_float(wh << 16),
                    o3 - __uint_as_float(wh & 0xffff0000u));
        *(uint32_t*)&g_ch[row1 * HID + d] = wh;
        *(uint32_t*)&g_cl[row1 * HID + d] = wl;
    }
}

// ---------------------------------------------------------------------------
extern "C" void kernel_launch(void* const* d_in, const int* in_sizes, int n_in,
                              void* d_out, int out_size)
{
    const float* x       = (const float*)d_in[0];
    const float* w_q     = (const float*)d_in[1];
    const float* w_kv    = (const float*)d_in[2];
    const float* w_dense = (const float*)d_in[3];
    float* out = (float*)d_out;

    float *qp, *kvp;
    __nv_bfloat16 *xh, *xl, *wqh, *wql, *wkvh, *wkvl, *wdh, *wdl, *ch, *cl;
    cudaGetSymbolAddress((void**)&qp,   g_q);
    cudaGetSymbolAddress((void**)&kvp,  g_kv);
    cudaGetSymbolAddress((void**)&xh,   g_xh);
    cudaGetSymbolAddress((void**)&xl,   g_xl);
    cudaGetSymbolAddress((void**)&wqh,  g_wqh);
    cudaGetSymbolAddress((void**)&wql,  g_wql);
    cudaGetSymbolAddress((void**)&wkvh, g_wkvh);
    cudaGetSymbolAddress((void**)&wkvl, g_wkvl);
    cudaGetSymbolAddress((void**)&wdh,  g_wdh);
    cudaGetSymbolAddress((void**)&wdl,  g_wdl);
    cudaGetSymbolAddress((void**)&ch,   g_ch);
    cudaGetSymbolAddress((void**)&cl,   g_cl);

    cudaFuncSetAttribute(gemm_mma, cudaFuncAttributeMaxDynamicSharedMemorySize, GEMM_SMEM);
    cudaFuncSetAttribute(flash_tc, cudaFuncAttributeMaxDynamicSharedMemorySize, FLASH_SMEM);

    // prep: split x; transpose+split weights
    prep_split<<<(BSTOK * KDIM / 4 + 255) / 256, 256>>>(x, xh, xl, BSTOK * KDIM / 4);
    transpose_split<<<dim3(HID / 32, KDIM / 32), dim3(32, 8)>>>(w_q, wqh, wql, HID);
    transpose_split<<<dim3((2 * NG * DK) / 32, KDIM / 32), dim3(32, 8)>>>(w_kv, wkvh, wkvl, 2 * NG * DK);
    transpose_split<<<dim3(HID / 32, KDIM / 32), dim3(32, 8)>>>(w_dense, wdh, wdl, HID);

    // projections
    gemm_mma<<<dim3(HID / 128, BSTOK / 128), 256, GEMM_SMEM>>>(xh, xl, wqh, wql, qp, HID);
    gemm_mma<<<dim3((2 * NG * DK) / 128, BSTOK / 128), 256, GEMM_SMEM>>>(xh, xl, wkvh, wkvl, kvp, 2 * NG * DK);

    // rope + splits + V transpose
    rope_split_q<<<(BSTOK * NH * 64) / 256, 256>>>();
    rope_split_k<<<(BSTOK * NG * 64) / 256, 256>>>();
    split_vt<<<dim3(SS / 32, DK / 32, BB * NG), dim3(32, 8)>>>();

    // attention (tensor cores)
    flash_tc<<<dim3(SS / FQT, NH, BB), 256, FLASH_SMEM>>>();

    // dense projection
    gemm_mma<<<dim3(HID / 128, BSTOK / 128), 256, GEMM_SMEM>>>(ch, cl, wdh, wdl, out, HID);
}

// round 11
// speedup vs baseline: 5.4241x; 1.4640x over previous
#include <cuda_runtime.h>
#include <cuda_fp16.h>
#include <cstdint>
#include <math.h>

#define BB    2
#define SS    2048
#define HID   2048
#define NH    16
#define NG    4
#define DK    128
#define NHPG  4
#define BSTOK (BB*SS)
#define KDIM  2048

// ---------------------------------------------------------------------------
// Scratch (__device__ globals; allocation-free rule)
// ---------------------------------------------------------------------------
static __device__ float g_q  [BSTOK * HID];            // Q proj fp32
static __device__ float g_kv [BSTOK * 2 * NG * DK];    // K|V proj fp32

static __device__ __half g_xh [BSTOK * KDIM];          // x hi/lo fp16
static __device__ __half g_xl [BSTOK * KDIM];
static __device__ __half g_wq [HID * KDIM];            // weights single fp16, transposed [N,K]
static __device__ __half g_wkv[(2*NG*DK) * KDIM];
static __device__ __half g_wd [HID * KDIM];

static __device__ __half g_qh [BSTOK * HID];           // rope'd, pre-scaled Q hi/lo
static __device__ __half g_ql [BSTOK * HID];
static __device__ __half g_kh [BSTOK * NG * DK];       // rope'd K single fp16
static __device__ __half g_vth[BB * NG * DK * SS];     // V transposed single fp16 [b,g][d][s]
static __device__ __half g_ch [BSTOK * KDIM];          // ctx hi/lo fp16
static __device__ __half g_cl [BSTOK * KDIM];

// ---------------------------------------------------------------------------
// helpers (base-target safe)
// ---------------------------------------------------------------------------
__device__ __forceinline__ void cp_async16(uint32_t s, const void* g) {
    asm volatile("cp.async.cg.shared.global [%0], [%1], 16;\n" :: "r"(s), "l"(g) : "memory");
}
__device__ __forceinline__ void cp_commit() {
    asm volatile("cp.async.commit_group;\n" ::: "memory");
}
__device__ __forceinline__ uint32_t lds_u32(uint32_t a) {
    uint32_t v; asm("ld.shared.b32 %0, [%1];" : "=r"(v) : "r"(a)); return v;
}
__device__ __forceinline__ void ldsm4(uint32_t* r, uint32_t a) {
    asm volatile("ldmatrix.sync.aligned.m8n8.x4.shared.b16 {%0,%1,%2,%3}, [%4];"
        : "=r"(r[0]), "=r"(r[1]), "=r"(r[2]), "=r"(r[3]) : "r"(a));
}
__device__ __forceinline__ uint32_t pack2h(float lo, float hi) {
    __half2 h = __floats2half2_rn(lo, hi);
    return *(uint32_t*)&h;
}
__device__ __forceinline__ void mma16816(float* c, const uint32_t* a, const uint32_t* b)
{
    asm volatile(
        "mma.sync.aligned.m16n8k16.row.col.f32.f16.f16.f32 "
        "{%0,%1,%2,%3}, {%4,%5,%6,%7}, {%8,%9}, {%0,%1,%2,%3};"
        : "+f"(c[0]), "+f"(c[1]), "+f"(c[2]), "+f"(c[3])
        : "r"(a[0]), "r"(a[1]), "r"(a[2]), "r"(a[3]), "r"(b[0]), "r"(b[1]));
}

// ---------------------------------------------------------------------------
// Prep: fp32 -> (fp16 hi, fp16 lo) split
// ---------------------------------------------------------------------------
__global__ void prep_split(const float* __restrict__ src,
                           __half* __restrict__ h,
                           __half* __restrict__ l, int n4)
{
    int i = blockIdx.x * blockDim.x + threadIdx.x;
    if (i >= n4) return;
    float4 v = ((const float4*)src)[i];
    float vv[4] = {v.x, v.y, v.z, v.w};
    __half hh[4], ll[4];
#pragma unroll
    for (int j = 0; j < 4; j++) {
        hh[j] = __float2half_rn(vv[j]);
        ll[j] = __float2half_rn(vv[j] - __half2float(hh[j]));
    }
    ((uint2*)h)[i] = *(uint2*)hh;
    ((uint2*)l)[i] = *(uint2*)ll;
}

// ---------------------------------------------------------------------------
// Prep: transpose W[K, N] fp32 -> WT [N, K] single fp16
// ---------------------------------------------------------------------------
__global__ void transpose_h(const float* __restrict__ W,
                            __half* __restrict__ T, int Ncols)
{
    __shared__ float tile[32][33];
    int n = blockIdx.x * 32 + threadIdx.x;
    int k0 = blockIdx.y * 32;
#pragma unroll
    for (int r = 0; r < 4; r++) {
        int k = k0 + threadIdx.y + r * 8;
        tile[threadIdx.y + r * 8][threadIdx.x] = W[(size_t)k * Ncols + n];
    }
    __syncthreads();
#pragma unroll
    for (int r = 0; r < 4; r++) {
        int nn = blockIdx.x * 32 + threadIdx.y + r * 8;
        int kk = k0 + threadIdx.x;
        T[(size_t)nn * KDIM + kk] = __float2half_rn(tile[threadIdx.x][threadIdx.y + r * 8]);
    }
}

// ---------------------------------------------------------------------------
// mma.sync GEMM: C = A @ B, A split hi/lo fp16 (exact), B single fp16.
// 2 mma terms. Tile 128x128, 8 warps (2M x 4N), 3-stage cp.async + ldmatrix.
// ---------------------------------------------------------------------------
#define LDB    144
#define TILEB  (128 * LDB)
#define STAGEB (3 * TILEB)          // Ah | Al | B
#define GEMM_SMEM (3 * STAGEB)      // 165888 B

__device__ __forceinline__ void load_chunk_mma(
    const __half* __restrict__ Ah, const __half* __restrict__ Al,
    const __half* __restrict__ Bm,
    int m0, int n0, int k0, uint32_t stage, int tid)
{
#pragma unroll
    for (int i = 0; i < 12; i++) {
        int lin = i * 256 + tid;            // 0..3071
        int t   = lin >> 10;                // 0:Ah 1:Al 2:B
        int rem = lin & 1023;
        int row = rem >> 3;
        int c   = rem & 7;
        const __half* base = (t == 0) ? Ah : (t == 1) ? Al : Bm;
        int grow = ((t < 2) ? m0 : n0) + row;
        const __half* gp = base + (size_t)grow * KDIM + k0 + c * 8;
        cp_async16(stage + t * TILEB + row * LDB + c * 16, gp);
    }
    cp_commit();
}

__global__ __launch_bounds__(256) void gemm_mma(
    const __half* __restrict__ Ah, const __half* __restrict__ Al,
    const __half* __restrict__ Bm,
    float* __restrict__ C, int N)
{
    extern __shared__ char smc[];
    uint32_t sb = (uint32_t)__cvta_generic_to_shared(smc);
    const int tid  = threadIdx.x;
    const int wid  = tid >> 5;
    const int lane = tid & 31;
    const int wm = wid >> 2;
    const int wn = wid & 3;
    const int m0 = blockIdx.y * 128;
    const int n0 = blockIdx.x * 128;
    const int r  = lane >> 2;
    const int kq = (lane & 3) * 2;

    const int qd = lane >> 3, lr = lane & 7;
    const uint32_t aBase = (uint32_t)((wm * 64 + (qd & 1) * 8 + lr) * LDB + (qd >> 1) * 16);
    const uint32_t bBase = (uint32_t)((wn * 32 + (qd >> 1) * 8 + lr) * LDB + (qd & 1) * 16);

    float acc[4][4][4];
#pragma unroll
    for (int mt = 0; mt < 4; mt++)
#pragma unroll
        for (int nt = 0; nt < 4; nt++)
#pragma unroll
            for (int j = 0; j < 4; j++) acc[mt][nt][j] = 0.0f;

    const int NC = KDIM / 64;           // 32
    load_chunk_mma(Ah, Al, Bm, m0, n0, 0, sb, tid);
    load_chunk_mma(Ah, Al, Bm, m0, n0, 64, sb + STAGEB, tid);

    for (int c = 0; c < NC; c++) {
        if (c + 1 < NC) {
            asm volatile("cp.async.wait_group 1;\n" ::: "memory");
        } else {
            asm volatile("cp.async.wait_group 0;\n" ::: "memory");
        }
        __syncthreads();
        if (c + 2 < NC)
            load_chunk_mma(Ah, Al, Bm, m0, n0, (c + 2) * 64,
                           sb + (uint32_t)((c + 2) % 3) * STAGEB, tid);

        const uint32_t stg = sb + (uint32_t)(c % 3) * STAGEB;

#pragma unroll
        for (int ks = 0; ks < 4; ks++) {
            const uint32_t koff = (uint32_t)ks * 32;
            uint32_t ah[4][4], al[4][4], bm[2][4];
#pragma unroll
            for (int mt = 0; mt < 4; mt++)
                ldsm4(ah[mt], stg + aBase + (uint32_t)mt * (16 * LDB) + koff);
#pragma unroll
            for (int mt = 0; mt < 4; mt++)
                ldsm4(al[mt], stg + TILEB + aBase + (uint32_t)mt * (16 * LDB) + koff);
#pragma unroll
            for (int p = 0; p < 2; p++)
                ldsm4(bm[p], stg + 2 * TILEB + bBase + (uint32_t)p * (16 * LDB) + koff);

#pragma unroll
            for (int mt = 0; mt < 4; mt++)
#pragma unroll
                for (int nt = 0; nt < 4; nt++) {
                    const uint32_t* bp = &bm[nt >> 1][(nt & 1) * 2];
                    mma16816(acc[mt][nt], ah[mt], bp);
                    mma16816(acc[mt][nt], al[mt], bp);
                }
        }
    }

#pragma unroll
    for (int mt = 0; mt < 4; mt++) {
#pragma unroll
        for (int nt = 0; nt < 4; nt++) {
            int row = m0 + wm * 64 + mt * 16 + r;
            int col = n0 + wn * 32 + nt * 8 + kq;
            *(float2*)&C[(size_t)row * N + col]       = make_float2(acc[mt][nt][0], acc[mt][nt][1]);
            *(float2*)&C[(size_t)(row + 8) * N + col] = make_float2(acc[mt][nt][2], acc[mt][nt][3]);
        }
    }
}

// ---------------------------------------------------------------------------
// RoPE + scale + fp16 split (Q), RoPE + single fp16 (K), V transpose fp16
// ---------------------------------------------------------------------------
#define QSCALE 0.08838834764831845f

__global__ void rope_split_q()
{
    int idx = blockIdx.x * blockDim.x + threadIdx.x;   // BSTOK*NH*64
    int j   = idx & 63;
    int h   = (idx >> 6) & (NH - 1);
    int tok = idx >> 10;
    if (tok >= BSTOK) return;
    int t = tok & (SS - 1);
    size_t base = (size_t)tok * HID + h * DK + j;
    float x1 = g_q[base], x2 = g_q[base + 64];
    float invf = exp2f(-0.20762050593045935f * (float)j);
    float f = (float)t * invf;
    float c, s;
    sincosf(f, &s, &c);
    float y1 = (x1 * c - x2 * s) * QSCALE;
    float y2 = (x2 * c + x1 * s) * QSCALE;
    __half h1 = __float2half_rn(y1);
    __half h2 = __float2half_rn(y2);
    g_qh[base]      = h1;
    g_qh[base + 64] = h2;
    g_ql[base]      = __float2half_rn(y1 - __half2float(h1));
    g_ql[base + 64] = __float2half_rn(y2 - __half2float(h2));
}

__global__ void rope_k()
{
    int idx = blockIdx.x * blockDim.x + threadIdx.x;   // BSTOK*NG*64
    int j   = idx & 63;
    int g   = (idx >> 6) & (NG - 1);
    int tok = idx >> 8;
    if (tok >= BSTOK) return;
    int t = tok & (SS - 1);
    size_t src = (size_t)tok * (2 * NG * DK) + g * DK + j;   // K half
    float x1 = g_kv[src], x2 = g_kv[src + 64];
    float invf = exp2f(-0.20762050593045935f * (float)j);
    float f = (float)t * invf;
    float c, s;
    sincosf(f, &s, &c);
    size_t dst = (size_t)tok * (NG * DK) + g * DK + j;
    g_kh[dst]      = __float2half_rn(x1 * c - x2 * s);
    g_kh[dst + 64] = __float2half_rn(x2 * c + x1 * s);
}

__global__ void vt_h()   // grid (SS/32, DK/32, BB*NG), block (32,8)
{
    __shared__ float tile[32][33];
    int bg = blockIdx.z;
    int b  = bg >> 2, g = bg & 3;
    int s0 = blockIdx.x * 32, d0 = blockIdx.y * 32;
#pragma unroll
    for (int r = 0; r < 4; r++) {
        int s = s0 + threadIdx.y + r * 8;
        tile[threadIdx.y + r * 8][threadIdx.x] =
            g_kv[(size_t)(b * SS + s) * (2 * NG * DK) + NG * DK + g * DK + d0 + threadIdx.x];
    }
    __syncthreads();
#pragma unroll
    for (int r = 0; r < 4; r++) {
        int d = d0 + threadIdx.y + r * 8;
        int s = s0 + threadIdx.x;
        size_t dst = ((size_t)bg * DK + d) * SS + s;
        g_vth[dst] = __float2half_rn(tile[threadIdx.x][threadIdx.y + r * 8]);
    }
}

// ---------------------------------------------------------------------------
// Flash attention fp16: QK = Qh*K + Ql*K (2 terms), PV = P*V (1 term), causal.
// Block: 256 thr = 8 warps, each warp 16 query rows. 128 q x 64 k tiles.
// ---------------------------------------------------------------------------
#define FQT 128
#define FKT 64
#define OFF_QH 0
#define OFF_QL (FQT*272)
#define STG0   (2*FQT*272)               // 69632
#define STG_K  0
#define STG_V  (FKT*272)                 // 17408
#define STG_SZ (FKT*272 + FQT*144)       // 35840
#define FLASH_SMEM (STG0 + 2*STG_SZ)     // 141312

__device__ __forceinline__ void flash_load_kv(int b, int g, int kbase, uint32_t stg, int tid)
{
#pragma unroll
    for (int i = 0; i < 8; i++) {
        int lin = i * 256 + tid;
        if (lin < 1024) {                 // K tile: 64 rows x 16 chunks
            int row = lin >> 4, c = lin & 15;
            const __half* src = g_kh
                + (size_t)(b * SS + kbase + row) * (NG * DK) + g * DK + c * 8;
            cp_async16(stg + STG_K + row * 272 + c * 16, src);
        } else {                          // Vt tile: 128 rows x 8 chunks
            int lin2 = lin - 1024;
            int row = lin2 >> 3, c = lin2 & 7;
            const __half* src = g_vth
                + ((size_t)(b * NG + g) * DK + row) * SS + kbase + c * 8;
            cp_async16(stg + STG_V + row * 144 + c * 16, src);
        }
    }
    cp_commit();
}

__global__ __launch_bounds__(256) void flash_tc()
{
    extern __shared__ char smc[];
    uint32_t sb = (uint32_t)__cvta_generic_to_shared(smc);
    const int tid  = threadIdx.x;
    const int wid  = tid >> 5;
    const int lane = tid & 31;
    const int qt = gridDim.x - 1 - blockIdx.x;    // heavy tiles first
    const int h  = blockIdx.y;
    const int b  = blockIdx.z;
    const int g  = h / NHPG;
    const int q0 = qt * FQT;
    const int r  = lane >> 2;
    const int kq = (lane & 3) * 2;

    // load Q hi/lo tile (once)
#pragma unroll
    for (int i = 0; i < 16; i++) {
        int lin = i * 256 + tid;                  // 0..4095
        int t   = lin >> 11;
        int rem = lin & 2047;
        int row = rem >> 4, c = rem & 15;
        const __half* src = (t ? g_ql : g_qh)
            + (size_t)(b * SS + q0 + row) * HID + h * DK + c * 8;
        cp_async16(sb + (t ? OFF_QL : OFF_QH) + row * 272 + c * 16, src);
    }
    cp_commit();

    const int numc = 2 * (qt + 1);
    flash_load_kv(b, g, 0, sb + STG0, tid);

    float m0 = -1e30f, m1 = -1e30f, l0 = 0.0f, l1 = 0.0f;
    float acc[16][4];
#pragma unroll
    for (int nt2 = 0; nt2 < 16; nt2++)
#pragma unroll
        for (int j = 0; j < 4; j++) acc[nt2][j] = 0.0f;

    const uint32_t qh_base = sb + OFF_QH + (wid * 16 + r) * 272 + kq * 2;

    for (int kc = 0; kc < numc; kc++) {
        const uint32_t stg = sb + STG0 + (uint32_t)(kc & 1) * STG_SZ;
        const int kbase = kc * FKT;
        if (kc + 1 < numc) {
            flash_load_kv(b, g, (kc + 1) * FKT, sb + STG0 + (uint32_t)((kc + 1) & 1) * STG_SZ, tid);
            asm volatile("cp.async.wait_group 1;\n" ::: "memory");
        } else {
            asm volatile("cp.async.wait_group 0;\n" ::: "memory");
        }
        __syncthreads();

        // ---- S = Q K^T (Qh + Ql, K single) ----
        float sc[8][4];
#pragma unroll
        for (int nt = 0; nt < 8; nt++)
#pragma unroll
            for (int j = 0; j < 4; j++) sc[nt][j] = 0.0f;

#pragma unroll
        for (int kd = 0; kd < 8; kd++) {
            uint32_t ah[4], al[4];
            uint32_t qa = qh_base + kd * 32;
            ah[0] = lds_u32(qa);
            ah[1] = lds_u32(qa + 8 * 272);
            ah[2] = lds_u32(qa + 16);
            ah[3] = lds_u32(qa + 8 * 272 + 16);
            qa += (OFF_QL - OFF_QH);
            al[0] = lds_u32(qa);
            al[1] = lds_u32(qa + 8 * 272);
            al[2] = lds_u32(qa + 16);
            al[3] = lds_u32(qa + 8 * 272 + 16);
#pragma unroll
            for (int nt = 0; nt < 8; nt++) {
                uint32_t kb = stg + STG_K + (nt * 8 + r) * 272 + kq * 2 + kd * 32;
                uint32_t bm[2] = {lds_u32(kb), lds_u32(kb + 16)};
                mma16816(sc[nt], ah, bm);
                mma16816(sc[nt], al, bm);
            }
        }

        // ---- causal mask ----
        if (kbase + FKT > q0) {
            const int row0g = q0 + wid * 16 + r;
#pragma unroll
            for (int nt = 0; nt < 8; nt++) {
                int key = kbase + nt * 8 + kq;
                if (key     > row0g)     sc[nt][0] = -1e30f;
                if (key + 1 > row0g)     sc[nt][1] = -1e30f;
                if (key     > row0g + 8) sc[nt][2] = -1e30f;
                if (key + 1 > row0g + 8) sc[nt][3] = -1e30f;
            }
        }

        // ---- online softmax ----
        float mx0 = -1e30f, mx1 = -1e30f;
#pragma unroll
        for (int nt = 0; nt < 8; nt++) {
            mx0 = fmaxf(mx0, fmaxf(sc[nt][0], sc[nt][1]));
            mx1 = fmaxf(mx1, fmaxf(sc[nt][2], sc[nt][3]));
        }
        mx0 = fmaxf(mx0, __shfl_xor_sync(0xffffffffu, mx0, 1));
        mx0 = fmaxf(mx0, __shfl_xor_sync(0xffffffffu, mx0, 2));
        mx1 = fmaxf(mx1, __shfl_xor_sync(0xffffffffu, mx1, 1));
        mx1 = fmaxf(mx1, __shfl_xor_sync(0xffffffffu, mx1, 2));
        float mn0 = fmaxf(m0, mx0), mn1 = fmaxf(m1, mx1);
        float c0 = __expf(m0 - mn0), c1 = __expf(m1 - mn1);
        float sum0 = 0.0f, sum1 = 0.0f;
#pragma unroll
        for (int nt = 0; nt < 8; nt++) {
            sc[nt][0] = __expf(sc[nt][0] - mn0); sum0 += sc[nt][0];
            sc[nt][1] = __expf(sc[nt][1] - mn0); sum0 += sc[nt][1];
            sc[nt][2] = __expf(sc[nt][2] - mn1); sum1 += sc[nt][2];
            sc[nt][3] = __expf(sc[nt][3] - mn1); sum1 += sc[nt][3];
        }
        sum0 += __shfl_xor_sync(0xffffffffu, sum0, 1);
        sum0 += __shfl_xor_sync(0xffffffffu, sum0, 2);
        sum1 += __shfl_xor_sync(0xffffffffu, sum1, 1);
        sum1 += __shfl_xor_sync(0xffffffffu, sum1, 2);
        l0 = l0 * c0 + sum0;  m0 = mn0;
        l1 = l1 * c1 + sum1;  m1 = mn1;
#pragma unroll
        for (int nt2 = 0; nt2 < 16; nt2++) {
            acc[nt2][0] *= c0; acc[nt2][1] *= c0;
            acc[nt2][2] *= c1; acc[nt2][3] *= c1;
        }

        // ---- O += P V (single fp16) ----
#pragma unroll
        for (int kk = 0; kk < 4; kk++) {
            uint32_t ph[4];
#pragma unroll
            for (int t4 = 0; t4 < 4; t4++) {
                int nt = 2 * kk + (t4 >> 1);
                ph[t4] = pack2h(sc[nt][(t4 & 1) * 2], sc[nt][(t4 & 1) * 2 + 1]);
            }
#pragma unroll
            for (int nt2 = 0; nt2 < 16; nt2++) {
                uint32_t vb = stg + STG_V + (nt2 * 8 + r) * 144 + (kk * 16 + kq) * 2;
                uint32_t bm[2] = {lds_u32(vb), lds_u32(vb + 16)};
                mma16816(acc[nt2], ph, bm);
            }
        }
        __syncthreads();
    }

    // ---- epilogue: normalize and write ctx hi/lo fp16 splits ----
    float inv0 = 1.0f / l0, inv1 = 1.0f / l1;
    size_t row0 = (size_t)(b * SS + q0 + wid * 16 + r);
    size_t row1 = row0 + 8;
#pragma unroll
    for (int nt2 = 0; nt2 < 16; nt2++) {
        int d = h * DK + nt2 * 8 + kq;
        {
            float o0 = acc[nt2][0] * inv0, o1 = acc[nt2][1] * inv0;
            __half h0 = __float2half_rn(o0), h1 = __float2half_rn(o1);
            *(uint32_t*)&g_ch[row0 * HID + d] =
                ((uint32_t)__half_as_ushort(h1) << 16) | __half_as_ushort(h0);
            *(uint32_t*)&g_cl[row0 * HID + d] =
                pack2h(o0 - __half2float(h0), o1 - __half2float(h1));
        }
        {
            float o2 = acc[nt2][2] * inv1, o3 = acc[nt2][3] * inv1;
            __half h2 = __float2half_rn(o2), h3 = __float2half_rn(o3);
            *(uint32_t*)&g_ch[row1 * HID + d] =
                ((uint32_t)__half_as_ushort(h3) << 16) | __half_as_ushort(h2);
            *(uint32_t*)&g_cl[row1 * HID + d] =
                pack2h(o2 - __half2float(h2), o3 - __half2float(h3));
        }
    }
}

// ---------------------------------------------------------------------------
extern "C" void kernel_launch(void* const* d_in, const int* in_sizes, int n_in,
                              void* d_out, int out_size)
{
    const float* x       = (const float*)d_in[0];
    const float* w_q     = (const float*)d_in[1];
    const float* w_kv    = (const float*)d_in[2];
    const float* w_dense = (const float*)d_in[3];
    float* out = (float*)d_out;

    float *qp, *kvp;
    __half *xh, *xl, *wq, *wkv, *wd, *ch, *cl;
    cudaGetSymbolAddress((void**)&qp,  g_q);
    cudaGetSymbolAddress((void**)&kvp, g_kv);
    cudaGetSymbolAddress((void**)&xh,  g_xh);
    cudaGetSymbolAddress((void**)&xl,  g_xl);
    cudaGetSymbolAddress((void**)&wq,  g_wq);
    cudaGetSymbolAddress((void**)&wkv, g_wkv);
    cudaGetSymbolAddress((void**)&wd,  g_wd);
    cudaGetSymbolAddress((void**)&ch,  g_ch);
    cudaGetSymbolAddress((void**)&cl,  g_cl);

    cudaFuncSetAttribute(gemm_mma, cudaFuncAttributeMaxDynamicSharedMemorySize, GEMM_SMEM);
    cudaFuncSetAttribute(flash_tc, cudaFuncAttributeMaxDynamicSharedMemorySize, FLASH_SMEM);

    // prep: split x; transpose weights (single fp16)
    prep_split<<<(BSTOK * KDIM / 4 + 255) / 256, 256>>>(x, xh, xl, BSTOK * KDIM / 4);
    transpose_h<<<dim3(HID / 32, KDIM / 32), dim3(32, 8)>>>(w_q, wq, HID);
    transpose_h<<<dim3((2 * NG * DK) / 32, KDIM / 32), dim3(32, 8)>>>(w_kv, wkv, 2 * NG * DK);
    transpose_h<<<dim3(HID / 32, KDIM / 32), dim3(32, 8)>>>(w_dense, wd, HID);

    // projections (fp16 x2)
    gemm_mma<<<dim3(HID / 128, BSTOK / 128), 256, GEMM_SMEM>>>(xh, xl, wq, qp, HID);
    gemm_mma<<<dim3((2 * NG * DK) / 128, BSTOK / 128), 256, GEMM_SMEM>>>(xh, xl, wkv, kvp, 2 * NG * DK);

    // rope + splits + V transpose
    rope_split_q<<<(BSTOK * NH * 64) / 256, 256>>>();
    rope_k<<<(BSTOK * NG * 64) / 256, 256>>>();
    vt_h<<<dim3(SS / 32, DK / 32, BB * NG), dim3(32, 8)>>>();

    // attention (tensor cores, fp16)
    flash_tc<<<dim3(SS / FQT, NH, BB), 256, FLASH_SMEM>>>();

    // dense projection (fp16 x2)
    gemm_mma<<<dim3(HID / 128, BSTOK / 128), 256, GEMM_SMEM>>>(ch, cl, wd, out, HID);
}

// round 12
// speedup vs baseline: 8.6933x; 1.6027x over previous
#include <cuda_runtime.h>
#include <cuda_fp16.h>
#include <cstdint>
#include <math.h>

#define BB    2
#define SS    2048
#define HID   2048
#define NH    16
#define NG    4
#define DK    128
#define NHPG  4
#define BSTOK (BB*SS)
#define KDIM  2048

// ---------------------------------------------------------------------------
// Scratch (__device__ globals; allocation-free rule)
// ---------------------------------------------------------------------------
static __device__ float g_q  [BSTOK * HID];            // Q proj fp32
static __device__ float g_kv [BSTOK * 2 * NG * DK];    // K|V proj fp32

static __device__ __half g_xh [BSTOK * KDIM];          // x single fp16
static __device__ __half g_wq [HID * KDIM];            // weights fp16, transposed [N,K]
static __device__ __half g_wkv[(2*NG*DK) * KDIM];
static __device__ __half g_wd [HID * KDIM];

static __device__ __half g_qh [BSTOK * HID];           // rope'd, pre-scaled Q fp16
static __device__ __half g_kh [BSTOK * NG * DK];       // rope'd K fp16
static __device__ __half g_vth[BB * NG * DK * SS];     // V transposed fp16 [b,g][d][s]
static __device__ __half g_ch [BSTOK * KDIM];          // ctx fp16

// ---------------------------------------------------------------------------
// helpers (base-target safe)
// ---------------------------------------------------------------------------
__device__ __forceinline__ void cp_async16(uint32_t s, const void* g) {
    asm volatile("cp.async.cg.shared.global [%0], [%1], 16;\n" :: "r"(s), "l"(g) : "memory");
}
__device__ __forceinline__ void cp_commit() {
    asm volatile("cp.async.commit_group;\n" ::: "memory");
}
__device__ __forceinline__ uint32_t lds_u32(uint32_t a) {
    uint32_t v; asm("ld.shared.b32 %0, [%1];" : "=r"(v) : "r"(a)); return v;
}
__device__ __forceinline__ void ldsm4(uint32_t* r, uint32_t a) {
    asm volatile("ldmatrix.sync.aligned.m8n8.x4.shared.b16 {%0,%1,%2,%3}, [%4];"
        : "=r"(r[0]), "=r"(r[1]), "=r"(r[2]), "=r"(r[3]) : "r"(a));
}
__device__ __forceinline__ uint32_t pack2h(float lo, float hi) {
    __half2 h = __floats2half2_rn(lo, hi);
    return *(uint32_t*)&h;
}
__device__ __forceinline__ void mma16816(float* c, const uint32_t* a, const uint32_t* b)
{
    asm volatile(
        "mma.sync.aligned.m16n8k16.row.col.f32.f16.f16.f32 "
        "{%0,%1,%2,%3}, {%4,%5,%6,%7}, {%8,%9}, {%0,%1,%2,%3};"
        : "+f"(c[0]), "+f"(c[1]), "+f"(c[2]), "+f"(c[3])
        : "r"(a[0]), "r"(a[1]), "r"(a[2]), "r"(a[3]), "r"(b[0]), "r"(b[1]));
}

// ---------------------------------------------------------------------------
// Prep: fp32 -> fp16 convert
// ---------------------------------------------------------------------------
__global__ void prep_h(const float* __restrict__ src, __half* __restrict__ h, int n4)
{
    int i = blockIdx.x * blockDim.x + threadIdx.x;
    if (i >= n4) return;
    float4 v = ((const float4*)src)[i];
    __half hh[4] = {__float2half_rn(v.x), __float2half_rn(v.y),
                    __float2half_rn(v.z), __float2half_rn(v.w)};
    ((uint2*)h)[i] = *(uint2*)hh;
}

// ---------------------------------------------------------------------------
// Prep: transpose W[K, N] fp32 -> WT [N, K] fp16
// ---------------------------------------------------------------------------
__global__ void transpose_h(const float* __restrict__ W,
                            __half* __restrict__ T, int Ncols)
{
    __shared__ float tile[32][33];
    int n = blockIdx.x * 32 + threadIdx.x;
    int k0 = blockIdx.y * 32;
#pragma unroll
    for (int r = 0; r < 4; r++) {
        int k = k0 + threadIdx.y + r * 8;
        tile[threadIdx.y + r * 8][threadIdx.x] = W[(size_t)k * Ncols + n];
    }
    __syncthreads();
#pragma unroll
    for (int r = 0; r < 4; r++) {
        int nn = blockIdx.x * 32 + threadIdx.y + r * 8;
        int kk = k0 + threadIdx.x;
        T[(size_t)nn * KDIM + kk] = __float2half_rn(tile[threadIdx.x][threadIdx.y + r * 8]);
    }
}

// ---------------------------------------------------------------------------
// mma.sync GEMM: C = A @ B, both single fp16, fp32 accum. 1 mma term.
// Tile 128x128, 8 warps (2M x 4N), 3-stage cp.async + ldmatrix.
// ---------------------------------------------------------------------------
#define LDB    144
#define TILEB  (128 * LDB)
#define STAGEB (2 * TILEB)          // A | B
#define GEMM_SMEM (3 * STAGEB)      // 110592 B

__device__ __forceinline__ void load_chunk_mma(
    const __half* __restrict__ A, const __half* __restrict__ Bm,
    int m0, int n0, int k0, uint32_t stage, int tid)
{
#pragma unroll
    for (int i = 0; i < 8; i++) {
        int lin = i * 256 + tid;            // 0..2047
        int t   = lin >> 10;                // 0:A 1:B
        int rem = lin & 1023;
        int row = rem >> 3;
        int c   = rem & 7;
        const __half* base = t ? Bm : A;
        int grow = (t ? n0 : m0) + row;
        cp_async16(stage + t * TILEB + row * LDB + c * 16,
                   base + (size_t)grow * KDIM + k0 + c * 8);
    }
    cp_commit();
}

__global__ __launch_bounds__(256) void gemm_mma(
    const __half* __restrict__ A, const __half* __restrict__ Bm,
    float* __restrict__ C, int N)
{
    extern __shared__ char smc[];
    uint32_t sb = (uint32_t)__cvta_generic_to_shared(smc);
    const int tid  = threadIdx.x;
    const int wid  = tid >> 5;
    const int lane = tid & 31;
    const int wm = wid >> 2;
    const int wn = wid & 3;
    const int m0 = blockIdx.y * 128;
    const int n0 = blockIdx.x * 128;
    const int r  = lane >> 2;
    const int kq = (lane & 3) * 2;

    const int qd = lane >> 3, lr = lane & 7;
    const uint32_t aBase = (uint32_t)((wm * 64 + (qd & 1) * 8 + lr) * LDB + (qd >> 1) * 16);
    const uint32_t bBase = (uint32_t)((wn * 32 + (qd >> 1) * 8 + lr) * LDB + (qd & 1) * 16);

    float acc[4][4][4];
#pragma unroll
    for (int mt = 0; mt < 4; mt++)
#pragma unroll
        for (int nt = 0; nt < 4; nt++)
#pragma unroll
            for (int j = 0; j < 4; j++) acc[mt][nt][j] = 0.0f;

    const int NC = KDIM / 64;           // 32
    load_chunk_mma(A, Bm, m0, n0, 0, sb, tid);
    load_chunk_mma(A, Bm, m0, n0, 64, sb + STAGEB, tid);

    for (int c = 0; c < NC; c++) {
        if (c + 1 < NC) {
            asm volatile("cp.async.wait_group 1;\n" ::: "memory");
        } else {
            asm volatile("cp.async.wait_group 0;\n" ::: "memory");
        }
        __syncthreads();
        if (c + 2 < NC)
            load_chunk_mma(A, Bm, m0, n0, (c + 2) * 64,
                           sb + (uint32_t)((c + 2) % 3) * STAGEB, tid);

        const uint32_t stg = sb + (uint32_t)(c % 3) * STAGEB;

#pragma unroll
        for (int ks = 0; ks < 4; ks++) {
            const uint32_t koff = (uint32_t)ks * 32;
            uint32_t ah[4][4], bm[2][4];
#pragma unroll
            for (int mt = 0; mt < 4; mt++)
                ldsm4(ah[mt], stg + aBase + (uint32_t)mt * (16 * LDB) + koff);
#pragma unroll
            for (int p = 0; p < 2; p++)
                ldsm4(bm[p], stg + TILEB + bBase + (uint32_t)p * (16 * LDB) + koff);

#pragma unroll
            for (int mt = 0; mt < 4; mt++)
#pragma unroll
                for (int nt = 0; nt < 4; nt++)
                    mma16816(acc[mt][nt], ah[mt], &bm[nt >> 1][(nt & 1) * 2]);
        }
    }

#pragma unroll
    for (int mt = 0; mt < 4; mt++) {
#pragma unroll
        for (int nt = 0; nt < 4; nt++) {
            int row = m0 + wm * 64 + mt * 16 + r;
            int col = n0 + wn * 32 + nt * 8 + kq;
            *(float2*)&C[(size_t)row * N + col]       = make_float2(acc[mt][nt][0], acc[mt][nt][1]);
            *(float2*)&C[(size_t)(row + 8) * N + col] = make_float2(acc[mt][nt][2], acc[mt][nt][3]);
        }
    }
}

// ---------------------------------------------------------------------------
// RoPE + scale -> fp16 (Q), RoPE -> fp16 (K), V transpose -> fp16
// ---------------------------------------------------------------------------
#define QSCALE 0.08838834764831845f

__global__ void rope_q_h()
{
    int idx = blockIdx.x * blockDim.x + threadIdx.x;   // BSTOK*NH*64
    int j   = idx & 63;
    int h   = (idx >> 6) & (NH - 1);
    int tok = idx >> 10;
    if (tok >= BSTOK) return;
    int t = tok & (SS - 1);
    size_t base = (size_t)tok * HID + h * DK + j;
    float x1 = g_q[base], x2 = g_q[base + 64];
    float invf = exp2f(-0.20762050593045935f * (float)j);
    float f = (float)t * invf;
    float c, s;
    sincosf(f, &s, &c);
    g_qh[base]      = __float2half_rn((x1 * c - x2 * s) * QSCALE);
    g_qh[base + 64] = __float2half_rn((x2 * c + x1 * s) * QSCALE);
}

__global__ void rope_k_h()
{
    int idx = blockIdx.x * blockDim.x + threadIdx.x;   // BSTOK*NG*64
    int j   = idx & 63;
    int g   = (idx >> 6) & (NG - 1);
    int tok = idx >> 8;
    if (tok >= BSTOK) return;
    int t = tok & (SS - 1);
    size_t src = (size_t)tok * (2 * NG * DK) + g * DK + j;   // K half
    float x1 = g_kv[src], x2 = g_kv[src + 64];
    float invf = exp2f(-0.20762050593045935f * (float)j);
    float f = (float)t * invf;
    float c, s;
    sincosf(f, &s, &c);
    size_t dst = (size_t)tok * (NG * DK) + g * DK + j;
    g_kh[dst]      = __float2half_rn(x1 * c - x2 * s);
    g_kh[dst + 64] = __float2half_rn(x2 * c + x1 * s);
}

__global__ void vt_h()   // grid (SS/32, DK/32, BB*NG), block (32,8)
{
    __shared__ float tile[32][33];
    int bg = blockIdx.z;
    int b  = bg >> 2, g = bg & 3;
    int s0 = blockIdx.x * 32, d0 = blockIdx.y * 32;
#pragma unroll
    for (int r = 0; r < 4; r++) {
        int s = s0 + threadIdx.y + r * 8;
        tile[threadIdx.y + r * 8][threadIdx.x] =
            g_kv[(size_t)(b * SS + s) * (2 * NG * DK) + NG * DK + g * DK + d0 + threadIdx.x];
    }
    __syncthreads();
#pragma unroll
    for (int r = 0; r < 4; r++) {
        int d = d0 + threadIdx.y + r * 8;
        int s = s0 + threadIdx.x;
        size_t dst = ((size_t)bg * DK + d) * SS + s;
        g_vth[dst] = __float2half_rn(tile[threadIdx.x][threadIdx.y + r * 8]);
    }
}

// ---------------------------------------------------------------------------
// Flash attention fp16: QK 1 term, PV 1 term, causal. fp32 softmax/accum.
// Block: 256 thr = 8 warps, each warp 16 query rows. 128 q x 64 k tiles.
// ---------------------------------------------------------------------------
#define FQT 128
#define FKT 64
#define OFF_Q  0
#define STG0   (FQT*272)                 // 34816
#define STG_K  0
#define STG_V  (FKT*272)                 // 17408
#define STG_SZ (FKT*272 + FQT*144)       // 35840
#define FLASH_SMEM (STG0 + 2*STG_SZ)     // 106496

__device__ __forceinline__ void flash_load_kv(int b, int g, int kbase, uint32_t stg, int tid)
{
#pragma unroll
    for (int i = 0; i < 8; i++) {
        int lin = i * 256 + tid;
        if (lin < 1024) {                 // K tile: 64 rows x 16 chunks
            int row = lin >> 4, c = lin & 15;
            const __half* src = g_kh
                + (size_t)(b * SS + kbase + row) * (NG * DK) + g * DK + c * 8;
            cp_async16(stg + STG_K + row * 272 + c * 16, src);
        } else {                          // Vt tile: 128 rows x 8 chunks
            int lin2 = lin - 1024;
            int row = lin2 >> 3, c = lin2 & 7;
            const __half* src = g_vth
                + ((size_t)(b * NG + g) * DK + row) * SS + kbase + c * 8;
            cp_async16(stg + STG_V + row * 144 + c * 16, src);
        }
    }
    cp_commit();
}

__global__ __launch_bounds__(256) void flash_tc()
{
    extern __shared__ char smc[];
    uint32_t sb = (uint32_t)__cvta_generic_to_shared(smc);
    const int tid  = threadIdx.x;
    const int wid  = tid >> 5;
    const int lane = tid & 31;
    const int qt = gridDim.x - 1 - blockIdx.x;    // heavy tiles first
    const int h  = blockIdx.y;
    const int b  = blockIdx.z;
    const int g  = h / NHPG;
    const int q0 = qt * FQT;
    const int r  = lane >> 2;
    const int kq = (lane & 3) * 2;

    // load Q tile (once): 128 rows x 16 chunks = 2048
#pragma unroll
    for (int i = 0; i < 8; i++) {
        int lin = i * 256 + tid;
        int row = lin >> 4, c = lin & 15;
        const __half* src = g_qh + (size_t)(b * SS + q0 + row) * HID + h * DK + c * 8;
        cp_async16(sb + OFF_Q + row * 272 + c * 16, src);
    }
    cp_commit();

    const int numc = 2 * (qt + 1);
    flash_load_kv(b, g, 0, sb + STG0, tid);

    float m0 = -1e30f, m1 = -1e30f, l0 = 0.0f, l1 = 0.0f;
    float acc[16][4];
#pragma unroll
    for (int nt2 = 0; nt2 < 16; nt2++)
#pragma unroll
        for (int j = 0; j < 4; j++) acc[nt2][j] = 0.0f;

    const uint32_t qh_base = sb + OFF_Q + (wid * 16 + r) * 272 + kq * 2;

    for (int kc = 0; kc < numc; kc++) {
        const uint32_t stg = sb + STG0 + (uint32_t)(kc & 1) * STG_SZ;
        const int kbase = kc * FKT;
        if (kc + 1 < numc) {
            flash_load_kv(b, g, (kc + 1) * FKT, sb + STG0 + (uint32_t)((kc + 1) & 1) * STG_SZ, tid);
            asm volatile("cp.async.wait_group 1;\n" ::: "memory");
        } else {
            asm volatile("cp.async.wait_group 0;\n" ::: "memory");
        }
        __syncthreads();

        // ---- S = Q K^T (single fp16) ----
        float sc[8][4];
#pragma unroll
        for (int nt = 0; nt < 8; nt++)
#pragma unroll
            for (int j = 0; j < 4; j++) sc[nt][j] = 0.0f;

#pragma unroll
        for (int kd = 0; kd < 8; kd++) {
            uint32_t ah[4];
            uint32_t qa = qh_base + kd * 32;
            ah[0] = lds_u32(qa);
            ah[1] = lds_u32(qa + 8 * 272);
            ah[2] = lds_u32(qa + 16);
            ah[3] = lds_u32(qa + 8 * 272 + 16);
#pragma unroll
            for (int nt = 0; nt < 8; nt++) {
                uint32_t kb = stg + STG_K + (nt * 8 + r) * 272 + kq * 2 + kd * 32;
                uint32_t bm[2] = {lds_u32(kb), lds_u32(kb + 16)};
                mma16816(sc[nt], ah, bm);
            }
        }

        // ---- causal mask ----
        if (kbase + FKT > q0) {
            const int row0g = q0 + wid * 16 + r;
#pragma unroll
            for (int nt = 0; nt < 8; nt++) {
                int key = kbase + nt * 8 + kq;
                if (key     > row0g)     sc[nt][0] = -1e30f;
                if (key + 1 > row0g)     sc[nt][1] = -1e30f;
                if (key     > row0g + 8) sc[nt][2] = -1e30f;
                if (key + 1 > row0g + 8) sc[nt][3] = -1e30f;
            }
        }

        // ---- online softmax ----
        float mx0 = -1e30f, mx1 = -1e30f;
#pragma unroll
        for (int nt = 0; nt < 8; nt++) {
            mx0 = fmaxf(mx0, fmaxf(sc[nt][0], sc[nt][1]));
            mx1 = fmaxf(mx1, fmaxf(sc[nt][2], sc[nt][3]));
        }
        mx0 = fmaxf(mx0, __shfl_xor_sync(0xffffffffu, mx0, 1));
        mx0 = fmaxf(mx0, __shfl_xor_sync(0xffffffffu, mx0, 2));
        mx1 = fmaxf(mx1, __shfl_xor_sync(0xffffffffu, mx1, 1));
        mx1 = fmaxf(mx1, __shfl_xor_sync(0xffffffffu, mx1, 2));
        float mn0 = fmaxf(m0, mx0), mn1 = fmaxf(m1, mx1);
        float c0 = __expf(m0 - mn0), c1 = __expf(m1 - mn1);
        float sum0 = 0.0f, sum1 = 0.0f;
#pragma unroll
        for (int nt = 0; nt < 8; nt++) {
            sc[nt][0] = __expf(sc[nt][0] - mn0); sum0 += sc[nt][0];
            sc[nt][1] = __expf(sc[nt][1] - mn0); sum0 += sc[nt][1];
            sc[nt][2] = __expf(sc[nt][2] - mn1); sum1 += sc[nt][2];
            sc[nt][3] = __expf(sc[nt][3] - mn1); sum1 += sc[nt][3];
        }
        sum0 += __shfl_xor_sync(0xffffffffu, sum0, 1);
        sum0 += __shfl_xor_sync(0xffffffffu, sum0, 2);
        sum1 += __shfl_xor_sync(0xffffffffu, sum1, 1);
        sum1 += __shfl_xor_sync(0xffffffffu, sum1, 2);
        l0 = l0 * c0 + sum0;  m0 = mn0;
        l1 = l1 * c1 + sum1;  m1 = mn1;
#pragma unroll
        for (int nt2 = 0; nt2 < 16; nt2++) {
            acc[nt2][0] *= c0; acc[nt2][1] *= c0;
            acc[nt2][2] *= c1; acc[nt2][3] *= c1;
        }

        // ---- O += P V (single fp16) ----
#pragma unroll
        for (int kk = 0; kk < 4; kk++) {
            uint32_t ph[4];
#pragma unroll
            for (int t4 = 0; t4 < 4; t4++) {
                int nt = 2 * kk + (t4 >> 1);
                ph[t4] = pack2h(sc[nt][(t4 & 1) * 2], sc[nt][(t4 & 1) * 2 + 1]);
            }
#pragma unroll
            for (int nt2 = 0; nt2 < 16; nt2++) {
                uint32_t vb = stg + STG_V + (nt2 * 8 + r) * 144 + (kk * 16 + kq) * 2;
                uint32_t bm[2] = {lds_u32(vb), lds_u32(vb + 16)};
                mma16816(acc[nt2], ph, bm);
            }
        }
        __syncthreads();
    }

    // ---- epilogue: normalize, write ctx fp16 ----
    float inv0 = 1.0f / l0, inv1 = 1.0f / l1;
    size_t row0 = (size_t)(b * SS + q0 + wid * 16 + r);
    size_t row1 = row0 + 8;
#pragma unroll
    for (int nt2 = 0; nt2 < 16; nt2++) {
        int d = h * DK + nt2 * 8 + kq;
        *(uint32_t*)&g_ch[row0 * HID + d] = pack2h(acc[nt2][0] * inv0, acc[nt2][1] * inv0);
        *(uint32_t*)&g_ch[row1 * HID + d] = pack2h(acc[nt2][2] * inv1, acc[nt2][3] * inv1);
    }
}

// ---------------------------------------------------------------------------
extern "C" void kernel_launch(void* const* d_in, const int* in_sizes, int n_in,
                              void* d_out, int out_size)
{
    const float* x       = (const float*)d_in[0];
    const float* w_q     = (const float*)d_in[1];
    const float* w_kv    = (const float*)d_in[2];
    const float* w_dense = (const float*)d_in[3];
    float* out = (float*)d_out;

    float *qp, *kvp;
    __half *xh, *wq, *wkv, *wd, *ch;
    cudaGetSymbolAddress((void**)&qp,  g_q);
    cudaGetSymbolAddress((void**)&kvp, g_kv);
    cudaGetSymbolAddress((void**)&xh,  g_xh);
    cudaGetSymbolAddress((void**)&wq,  g_wq);
    cudaGetSymbolAddress((void**)&wkv, g_wkv);
    cudaGetSymbolAddress((void**)&wd,  g_wd);
    cudaGetSymbolAddress((void**)&ch,  g_ch);

    cudaFuncSetAttribute(gemm_mma, cudaFuncAttributeMaxDynamicSharedMemorySize, GEMM_SMEM);
    cudaFuncSetAttribute(flash_tc, cudaFuncAttributeMaxDynamicSharedMemorySize, FLASH_SMEM);

    // prep: convert x; transpose weights
    prep_h<<<(BSTOK * KDIM / 4 + 255) / 256, 256>>>(x, xh, BSTOK * KDIM / 4);
    transpose_h<<<dim3(HID / 32, KDIM / 32), dim3(32, 8)>>>(w_q, wq, HID);
    transpose_h<<<dim3((2 * NG * DK) / 32, KDIM / 32), dim3(32, 8)>>>(w_kv, wkv, 2 * NG * DK);
    transpose_h<<<dim3(HID / 32, KDIM / 32), dim3(32, 8)>>>(w_dense, wd, HID);

    // projections (single fp16)
    gemm_mma<<<dim3(HID / 128, BSTOK / 128), 256, GEMM_SMEM>>>(xh, wq, qp, HID);
    gemm_mma<<<dim3((2 * NG * DK) / 128, BSTOK / 128), 256, GEMM_SMEM>>>(xh, wkv, kvp, 2 * NG * DK);

    // rope + V transpose
    rope_q_h<<<(BSTOK * NH * 64) / 256, 256>>>();
    rope_k_h<<<(BSTOK * NG * 64) / 256, 256>>>();
    vt_h<<<dim3(SS / 32, DK / 32, BB * NG), dim3(32, 8)>>>();

    // attention (tensor cores, fp16)
    flash_tc<<<dim3(SS / FQT, NH, BB), 256, FLASH_SMEM>>>();

    // dense projection
    gemm_mma<<<dim3(HID / 128, BSTOK / 128), 256, GEMM_SMEM>>>(ch, wd, out, HID);
}